// round 9
// baseline (speedup 1.0000x reference)
#include <cuda_runtime.h>
#include <math.h>

#define BATCH 32
#define NTOK  4096
#define NSLOT 8
#define DIM   512
#define HID   512
#define CHUNKS 32
#define TJ    128      // tokens per attention block
#define ROWS  256      // BATCH*NSLOT

// ---------------- device scratch (no cudaMalloc allowed) ----------------
__device__ float g_qn   [ROWS*DIM];
__device__ float g_q    [ROWS*DIM];
__device__ float g_qk   [ROWS*DIM];
__device__ float g_qb   [ROWS];
__device__ float g_upart[BATCH*CHUNKS*NSLOT*DIM];   // 16.8 MB partials
__device__ float g_spart[BATCH*CHUNKS*NSLOT];
__device__ float g_upre [ROWS*DIM];
__device__ float g_upd  [ROWS*DIM];
__device__ float g_gx   [ROWS*3*DIM];
__device__ float g_gh   [ROWS*3*DIM];
__device__ float g_y    [ROWS*DIM];
__device__ float g_h1   [ROWS*HID];

// ---------------- slot init: slots = mu + |sigma| * noise ----------------
__global__ void init_slots_kernel(const float* __restrict__ noise,
                                  const float* __restrict__ mu,
                                  const float* __restrict__ sg,
                                  float* __restrict__ slots)
{
    int idx = blockIdx.x * blockDim.x + threadIdx.x;
    if (idx >= ROWS*DIM) return;
    int c = idx & (DIM-1);
    slots[idx] = mu[c] + fabsf(sg[c]) * noise[idx];
}

// ---------------- LayerNorm over rows of [ROWS, 512], warp per row ----------------
__global__ void ln_rows_kernel(const float* __restrict__ X,
                               const float* __restrict__ g,
                               const float* __restrict__ b,
                               float* __restrict__ Y)
{
    int row = blockIdx.x * 8 + (threadIdx.x >> 5);
    int l   = threadIdx.x & 31;
    const float* x = X + (size_t)row * DIM;
    float xv[16];
    float sum = 0.f, ssq = 0.f;
#pragma unroll
    for (int s = 0; s < 4; s++) {
        float4 v = *(const float4*)&x[s*128 + l*4];
        xv[s*4+0]=v.x; xv[s*4+1]=v.y; xv[s*4+2]=v.z; xv[s*4+3]=v.w;
    }
#pragma unroll
    for (int t = 0; t < 16; t++) { sum += xv[t]; ssq += xv[t]*xv[t]; }
#pragma unroll
    for (int off = 16; off > 0; off >>= 1) {
        sum += __shfl_xor_sync(0xffffffffu, sum, off);
        ssq += __shfl_xor_sync(0xffffffffu, ssq, off);
    }
    float mean = sum * (1.f/DIM);
    float var  = ssq * (1.f/DIM) - mean*mean;
    float inv  = rsqrtf(var + 1e-5f);
    float* y = Y + (size_t)row * DIM;
#pragma unroll
    for (int s = 0; s < 4; s++) {
        int c = s*128 + l*4;
        float4 gv = *(const float4*)&g[c];
        float4 bv = *(const float4*)&b[c];
        float4 o;
        o.x = (xv[s*4+0]-mean)*inv*gv.x + bv.x;
        o.y = (xv[s*4+1]-mean)*inv*gv.y + bv.y;
        o.z = (xv[s*4+2]-mean)*inv*gv.z + bv.z;
        o.w = (xv[s*4+3]-mean)*inv*gv.w + bv.w;
        *(float4*)&y[c] = o;
    }
}

// ---------------- qb[row] = q[row] . bk ----------------
__global__ void dotb_kernel(const float* __restrict__ Q, const float* __restrict__ bk,
                            float* __restrict__ qb)
{
    int row = blockIdx.x * 8 + (threadIdx.x >> 5);
    int l   = threadIdx.x & 31;
    const float* q = Q + (size_t)row * DIM;
    float s = 0.f;
#pragma unroll
    for (int t = 0; t < 16; t++) {
        int c = l + 32*t;
        s += q[c] * __ldg(&bk[c]);
    }
#pragma unroll
    for (int off = 16; off > 0; off >>= 1) s += __shfl_xor_sync(0xffffffffu, s, off);
    if (l == 0) qb[row] = s;
}

// ---------------- small GEMM: C = act(A[M,K] @ op(B) + bias) (+res) ----------------
// TRANSB=true : B is [N,K] row-major (torch Linear weight),  C = A @ B^T
// TRANSB=false: B is [K,N] row-major,                        C = A @ B
template<bool TRANSB, int ACT, bool RESID>
__global__ __launch_bounds__(256) void gemm_kernel(
    const float* __restrict__ A, const float* __restrict__ B,
    const float* __restrict__ bias, const float* __restrict__ res,
    float* __restrict__ C, int M, int N, int K)
{
    const int BM=32, BN=64, BK=32;
    __shared__ float As[BK][BM+1];
    __shared__ float Bs[BK][BN+4];
    int tid = threadIdx.x;
    int m0 = blockIdx.x * BM;
    int n0 = blockIdx.y * BN;
    int tx = tid & 15;   // 16 * 4 = 64 cols
    int ty = tid >> 4;   // 16 * 2 = 32 rows
    float acc[2][4] = {{0.f,0.f,0.f,0.f},{0.f,0.f,0.f,0.f}};

    for (int k0 = 0; k0 < K; k0 += BK) {
        { // A tile -> As[k][m] (transposed, padded)
            int r  = tid >> 3;
            int kq = (tid & 7) * 4;
            float4 a = *(const float4*)&A[(size_t)(m0+r)*K + k0 + kq];
            As[kq+0][r]=a.x; As[kq+1][r]=a.y; As[kq+2][r]=a.z; As[kq+3][r]=a.w;
        }
        if (TRANSB) {
#pragma unroll
            for (int it = 0; it < 2; it++) {
                int qidx = tid + it*256;
                int n  = qidx >> 3;
                int kq = (qidx & 7) * 4;
                float4 v = *(const float4*)&B[(size_t)(n0+n)*K + k0 + kq];
                Bs[kq+0][n]=v.x; Bs[kq+1][n]=v.y; Bs[kq+2][n]=v.z; Bs[kq+3][n]=v.w;
            }
        } else {
#pragma unroll
            for (int it = 0; it < 2; it++) {
                int qidx = tid + it*256;
                int k  = qidx >> 4;
                int nq = (qidx & 15) * 4;
                *(float4*)&Bs[k][nq] = *(const float4*)&B[(size_t)(k0+k)*N + n0 + nq];
            }
        }
        __syncthreads();
#pragma unroll
        for (int kk = 0; kk < BK; kk++) {
            float a0 = As[kk][ty*2+0];
            float a1 = As[kk][ty*2+1];
            float4 b4 = *(const float4*)&Bs[kk][tx*4];
            acc[0][0]+=a0*b4.x; acc[0][1]+=a0*b4.y; acc[0][2]+=a0*b4.z; acc[0][3]+=a0*b4.w;
            acc[1][0]+=a1*b4.x; acc[1][1]+=a1*b4.y; acc[1][2]+=a1*b4.z; acc[1][3]+=a1*b4.w;
        }
        __syncthreads();
    }
#pragma unroll
    for (int i = 0; i < 2; i++) {
        int m = m0 + ty*2 + i;
#pragma unroll
        for (int j = 0; j < 4; j++) {
            int n = n0 + tx*4 + j;
            float v = acc[i][j];
            if (bias) v += __ldg(&bias[n]);
            if (ACT == 1) v = fmaxf(v, 0.f);
            if (RESID) v += res[(size_t)m*N + n];
            C[(size_t)m*N + n] = v;
        }
    }
}

// ---------------- fused attention pass over inputs ----------------
// Per block: one (batch, 128-token chunk). Recomputes LN(inputs) inline,
// dots_i = (qk_i . xln + qb_i)*scale, softmax over 8 slots, p += eps,
// accumulates U[i,:] += p_i * xln  and  S[i] += p_i  in registers,
// writes deterministic per-chunk partials.
__global__ __launch_bounds__(256) void attn_kernel(
    const float* __restrict__ X,
    const float* __restrict__ g_in, const float* __restrict__ be_in,
    const float* __restrict__ QK, const float* __restrict__ QB,
    float* __restrict__ Upart, float* __restrict__ Spart)
{
    __shared__ float qks[NSLOT][DIM];
    __shared__ float xs [NSLOT][DIM];
    __shared__ float gss[DIM];
    __shared__ float bss[DIM];
    __shared__ float ps [NSLOT][NSLOT];
    __shared__ float qbs[NSLOT];

    int b   = blockIdx.y;
    int ch  = blockIdx.x;
    int tid = threadIdx.x;
    int w = tid >> 5;
    int l = tid & 31;

    for (int i = tid*4; i < NSLOT*DIM; i += 256*4)
        *(float4*)&qks[0][i] = *(const float4*)&QK[(size_t)b*NSLOT*DIM + i];
    if (tid*4 < DIM) {
        *(float4*)&gss[tid*4] = *(const float4*)&g_in[tid*4];
        *(float4*)&bss[tid*4] = *(const float4*)&be_in[tid*4];
    }
    if (tid < NSLOT) qbs[tid] = QB[b*NSLOT + tid];
    __syncthreads();

    float U[16];
#pragma unroll
    for (int t = 0; t < 16; t++) U[t] = 0.f;
    float Sl = 0.f;

    const float scale = 0.04419417382415922f;   // 512^-0.5
    int j0 = ch * TJ;

    for (int gidx = 0; gidx < TJ/8; gidx++) {
        // ---- phase 1: warp w owns token j ----
        int j = j0 + gidx*8 + w;
        const float* xrow = X + ((size_t)b*NTOK + j)*DIM;
        float xv[16];
        float sum = 0.f, ssq = 0.f;
#pragma unroll
        for (int s = 0; s < 4; s++) {
            float4 v = *(const float4*)&xrow[s*128 + l*4];
            xv[s*4+0]=v.x; xv[s*4+1]=v.y; xv[s*4+2]=v.z; xv[s*4+3]=v.w;
        }
#pragma unroll
        for (int t = 0; t < 16; t++) { sum += xv[t]; ssq += xv[t]*xv[t]; }
#pragma unroll
        for (int off = 16; off > 0; off >>= 1) {
            sum += __shfl_xor_sync(0xffffffffu, sum, off);
            ssq += __shfl_xor_sync(0xffffffffu, ssq, off);
        }
        float mean = sum * (1.f/DIM);
        float var  = ssq * (1.f/DIM) - mean*mean;
        float inv  = rsqrtf(var + 1e-5f);

        float acc[8];
#pragma unroll
        for (int i = 0; i < 8; i++) acc[i] = 0.f;
#pragma unroll
        for (int s = 0; s < 4; s++) {
            int c = s*128 + l*4;
            float4 gv = *(const float4*)&gss[c];
            float4 bv = *(const float4*)&bss[c];
            float xn0 = (xv[s*4+0]-mean)*inv*gv.x + bv.x;
            float xn1 = (xv[s*4+1]-mean)*inv*gv.y + bv.y;
            float xn2 = (xv[s*4+2]-mean)*inv*gv.z + bv.z;
            float xn3 = (xv[s*4+3]-mean)*inv*gv.w + bv.w;
            *(float4*)&xs[w][c] = make_float4(xn0,xn1,xn2,xn3);
#pragma unroll
            for (int i = 0; i < 8; i++) {
                float4 qv = *(const float4*)&qks[i][c];
                acc[i] += qv.x*xn0 + qv.y*xn1 + qv.z*xn2 + qv.w*xn3;
            }
        }
#pragma unroll
        for (int off = 16; off > 0; off >>= 1) {
#pragma unroll
            for (int i = 0; i < 8; i++)
                acc[i] += __shfl_xor_sync(0xffffffffu, acc[i], off);
        }
        // softmax across the 8 slots (computed redundantly per lane)
        float mx = -1e30f;
#pragma unroll
        for (int i = 0; i < 8; i++) {
            acc[i] = (acc[i] + qbs[i]) * scale;
            mx = fmaxf(mx, acc[i]);
        }
        float se = 0.f;
#pragma unroll
        for (int i = 0; i < 8; i++) { acc[i] = expf(acc[i]-mx); se += acc[i]; }
        float rse = 1.f/se;
        if (l < 8) ps[w][l] = acc[l]*rse + 1e-8f;
        __syncthreads();

        // ---- phase 2: warp w owns slot w; lane l owns c = s*128 + 4l ----
#pragma unroll
        for (int t = 0; t < 8; t++) {
            float pt = ps[t][w];
            if (l == 0) Sl += pt;
#pragma unroll
            for (int s = 0; s < 4; s++) {
                float4 xq = *(const float4*)&xs[t][s*128 + l*4];
                U[s*4+0] += pt*xq.x;
                U[s*4+1] += pt*xq.y;
                U[s*4+2] += pt*xq.z;
                U[s*4+3] += pt*xq.w;
            }
        }
        __syncthreads();
    }

    float* up = Upart + (((size_t)b*CHUNKS + ch)*NSLOT + w)*DIM;
#pragma unroll
    for (int s = 0; s < 4; s++)
        *(float4*)&up[s*128 + l*4] = make_float4(U[s*4+0],U[s*4+1],U[s*4+2],U[s*4+3]);
    if (l == 0) Spart[(b*CHUNKS + ch)*NSLOT + w] = Sl;
}

// ---------------- reduce partials: Upre[b,i,:] = (sum_ch U)/ (sum_ch S) ----------------
__global__ void finish_kernel(const float* __restrict__ Upart,
                              const float* __restrict__ Spart,
                              float* __restrict__ Upre)
{
    int bi = blockIdx.x;            // 0..255 = b*8 + i
    int b = bi >> 3, i = bi & 7;
    int tid = threadIdx.x;          // 128 threads
    __shared__ float ssum_s;
    if (tid < 32) {
        float s = Spart[(b*CHUNKS + tid)*NSLOT + i];
#pragma unroll
        for (int off = 16; off > 0; off >>= 1) s += __shfl_xor_sync(0xffffffffu, s, off);
        if (tid == 0) ssum_s = s;
    }
    __syncthreads();
    float rs = 1.f / ssum_s;
    int c = tid * 4;
    float4 acc = make_float4(0.f,0.f,0.f,0.f);
    for (int chn = 0; chn < CHUNKS; chn++) {
        float4 v = *(const float4*)&Upart[(((size_t)b*CHUNKS + chn)*NSLOT + i)*DIM + c];
        acc.x += v.x; acc.y += v.y; acc.z += v.z; acc.w += v.w;
    }
    acc.x*=rs; acc.y*=rs; acc.z*=rs; acc.w*=rs;
    *(float4*)&Upre[(size_t)bi*DIM + c] = acc;
}

// ---------------- GRU cell elementwise (in-place on slots) ----------------
__global__ void gru_kernel(const float* __restrict__ gx, const float* __restrict__ gh,
                           float* __restrict__ slots)
{
    int idx = blockIdx.x * blockDim.x + threadIdx.x;
    if (idx >= ROWS*DIM) return;
    int m = idx >> 9;
    int c = idx & (DIM-1);
    const float* gxm = gx + (size_t)m*3*DIM;
    const float* ghm = gh + (size_t)m*3*DIM;
    float r = 1.f/(1.f + expf(-(gxm[c]        + ghm[c])));
    float z = 1.f/(1.f + expf(-(gxm[DIM+c]    + ghm[DIM+c])));
    float n = tanhf(gxm[2*DIM+c] + r*ghm[2*DIM+c]);
    float h = slots[idx];
    slots[idx] = (1.f - z)*n + z*h;
}

// ---------------- host orchestration (graph-capturable, alloc-free) ----------------
extern "C" void kernel_launch(void* const* d_in, const int* in_sizes, int n_in,
                              void* d_out, int out_size)
{
    const float* inputs = (const float*)d_in[0];
    const float* noise  = (const float*)d_in[1];
    const float* mu     = (const float*)d_in[2];
    const float* sg     = (const float*)d_in[3];
    const float* Wq = (const float*)d_in[4];
    const float* bq = (const float*)d_in[5];
    const float* Wk = (const float*)d_in[6];
    const float* bk = (const float*)d_in[7];
    const float* Wv = (const float*)d_in[8];
    const float* bv = (const float*)d_in[9];
    const float* W_ih = (const float*)d_in[10];
    const float* b_ih = (const float*)d_in[11];
    const float* W_hh = (const float*)d_in[12];
    const float* b_hh = (const float*)d_in[13];
    const float* W1 = (const float*)d_in[14];
    const float* b1 = (const float*)d_in[15];
    const float* W2 = (const float*)d_in[16];
    const float* b2 = (const float*)d_in[17];
    const float* gin  = (const float*)d_in[18];
    const float* bein = (const float*)d_in[19];
    const float* gsl  = (const float*)d_in[20];
    const float* besl = (const float*)d_in[21];
    const float* gff  = (const float*)d_in[22];
    const float* beff = (const float*)d_in[23];

    float* slots = (float*)d_out;

    void* p;
    cudaGetSymbolAddress(&p, g_qn);    float* qn    = (float*)p;
    cudaGetSymbolAddress(&p, g_q);     float* q     = (float*)p;
    cudaGetSymbolAddress(&p, g_qk);    float* qk    = (float*)p;
    cudaGetSymbolAddress(&p, g_qb);    float* qb    = (float*)p;
    cudaGetSymbolAddress(&p, g_upart); float* upart = (float*)p;
    cudaGetSymbolAddress(&p, g_spart); float* spart = (float*)p;
    cudaGetSymbolAddress(&p, g_upre);  float* upre  = (float*)p;
    cudaGetSymbolAddress(&p, g_upd);   float* upd   = (float*)p;
    cudaGetSymbolAddress(&p, g_gx);    float* gx    = (float*)p;
    cudaGetSymbolAddress(&p, g_gh);    float* gh    = (float*)p;
    cudaGetSymbolAddress(&p, g_y);     float* ybuf  = (float*)p;
    cudaGetSymbolAddress(&p, g_h1);    float* h1    = (float*)p;

    init_slots_kernel<<<(ROWS*DIM + 255)/256, 256>>>(noise, mu, sg, slots);

    for (int it = 0; it < 3; it++) {
        // q = LN(slots) @ Wq^T + bq ;  qk = q @ Wk ; qb = q . bk
        ln_rows_kernel<<<32, 256>>>(slots, gsl, besl, qn);
        gemm_kernel<true,0,false><<<dim3(8,8), 256>>>(qn, Wq, bq, nullptr, q, ROWS, DIM, DIM);
        gemm_kernel<false,0,false><<<dim3(8,8), 256>>>(q, Wk, nullptr, nullptr, qk, ROWS, DIM, DIM);
        dotb_kernel<<<32, 256>>>(q, bk, qb);

        // fused: LN(inputs) + dots + slot-softmax + eps + weighted accumulation
        attn_kernel<<<dim3(CHUNKS, BATCH), 256>>>(inputs, gin, bein, qk, qb, upart, spart);
        finish_kernel<<<ROWS, 128>>>(upart, spart, upre);

        // updates = Upre @ Wv^T + bv  (bv scaled by sum(attn)=1)
        gemm_kernel<true,0,false><<<dim3(8,8), 256>>>(upre, Wv, bv, nullptr, upd, ROWS, DIM, DIM);

        // GRU
        gemm_kernel<true,0,false><<<dim3(8,24), 256>>>(upd,   W_ih, b_ih, nullptr, gx, ROWS, 3*DIM, DIM);
        gemm_kernel<true,0,false><<<dim3(8,24), 256>>>(slots, W_hh, b_hh, nullptr, gh, ROWS, 3*DIM, DIM);
        gru_kernel<<<(ROWS*DIM + 255)/256, 256>>>(gx, gh, slots);

        // MLP residual
        ln_rows_kernel<<<32, 256>>>(slots, gff, beff, ybuf);
        gemm_kernel<true,1,false><<<dim3(8,8), 256>>>(ybuf, W1, b1, nullptr, h1, ROWS, HID, DIM);
        gemm_kernel<true,0,true ><<<dim3(8,8), 256>>>(h1,   W2, b2, slots,  slots, ROWS, DIM, HID);
    }
}

// round 10
// speedup vs baseline: 1.1657x; 1.1657x over previous
#include <cuda_runtime.h>
#include <math.h>

#define BATCH 32
#define NTOK  4096
#define NSLOT 8
#define DIM   512
#define CHUNKS 32
#define TJ    128
#define ROWS  256

typedef unsigned long long u64;

// ---------------- packed f32x2 helpers ----------------
__device__ __forceinline__ u64 pk2(float lo, float hi) {
    u64 r; asm("mov.b64 %0, {%1, %2};" : "=l"(r) : "f"(lo), "f"(hi)); return r;
}
__device__ __forceinline__ void upk2(u64 v, float& a, float& b) {
    asm("mov.b64 {%0, %1}, %2;" : "=f"(a), "=f"(b) : "l"(v));
}
__device__ __forceinline__ u64 fma2_(u64 a, u64 b, u64 c) {
    u64 d; asm("fma.rn.f32x2 %0, %1, %2, %3;" : "=l"(d) : "l"(a), "l"(b), "l"(c)); return d;
}
__device__ __forceinline__ u64 add2_(u64 a, u64 b) {
    u64 d; asm("add.rn.f32x2 %0, %1, %2;" : "=l"(d) : "l"(a), "l"(b)); return d;
}
__device__ __forceinline__ u64 mul2_(u64 a, u64 b) {
    u64 d; asm("mul.rn.f32x2 %0, %1, %2;" : "=l"(d) : "l"(a), "l"(b)); return d;
}

// ---------------- device scratch ----------------
__device__ float g_qn   [ROWS*DIM];
__device__ float g_qk   [ROWS*DIM];
__device__ float g_qb   [ROWS];
__device__ float g_Mqk  [DIM*DIM];
__device__ float g_rqk  [DIM];
__device__ float g_u    [DIM];
__device__ float g_c0   [1];
__device__ float g_upart[BATCH*CHUNKS*NSLOT*DIM];
__device__ float g_spart[BATCH*CHUNKS*NSLOT];
__device__ float g_upre [ROWS*DIM];
__device__ float g_upd  [ROWS*DIM];
__device__ float g_gx   [ROWS*3*DIM];
__device__ float g_gh   [ROWS*3*DIM];
__device__ float g_y    [ROWS*DIM];
__device__ float g_h1   [ROWS*DIM];

// ---------------- slot init ----------------
__global__ void init_slots_kernel(const float* __restrict__ noise,
                                  const float* __restrict__ mu,
                                  const float* __restrict__ sg,
                                  float* __restrict__ slots)
{
    int idx = blockIdx.x * blockDim.x + threadIdx.x;
    if (idx >= ROWS*DIM) return;
    int c = idx & (DIM-1);
    slots[idx] = mu[c] + fabsf(sg[c]) * noise[idx];
}

// ---------------- one-time vector precompute ----------------
// rqk[f] = sum_d bq[d]*Wk[d,f];  u[e] = sum_d Wq[d,e]*bk[d];  c0 = bq.bk
__global__ void precompute_vecs(const float* __restrict__ Wq, const float* __restrict__ Wk,
                                const float* __restrict__ bq, const float* __restrict__ bk,
                                float* __restrict__ rqk, float* __restrict__ uvec,
                                float* __restrict__ c0)
{
    int bid = blockIdx.x;
    int tid = threadIdx.x;
    if (bid < 4) {
        int f = bid*128 + tid;
        float acc = 0.f;
#pragma unroll 8
        for (int d = 0; d < DIM; d++) acc += __ldg(&bq[d]) * Wk[(size_t)d*DIM + f];
        rqk[f] = acc;
    } else if (bid < 8) {
        int e = (bid-4)*128 + tid;
        float acc = 0.f;
#pragma unroll 8
        for (int d = 0; d < DIM; d++) acc += __ldg(&bk[d]) * Wq[(size_t)d*DIM + e];
        uvec[e] = acc;
    } else {
        __shared__ float red[128];
        float acc = 0.f;
        for (int d = tid; d < DIM; d += 128) acc += bq[d]*bk[d];
        red[tid] = acc; __syncthreads();
        for (int s = 64; s > 0; s >>= 1) { if (tid < s) red[tid] += red[tid+s]; __syncthreads(); }
        if (tid == 0) *c0 = red[0];
    }
}

// ---------------- LayerNorm (+ optional fused qb = y.u + c0) ----------------
__global__ void ln_rows_kernel(const float* __restrict__ X,
                               const float* __restrict__ g,
                               const float* __restrict__ b,
                               float* __restrict__ Y,
                               const float* __restrict__ u,
                               float* __restrict__ qb,
                               const float* __restrict__ c0)
{
    int row = blockIdx.x * 8 + (threadIdx.x >> 5);
    int l   = threadIdx.x & 31;
    const float* x = X + (size_t)row * DIM;
    float xv[16];
    float sum = 0.f, ssq = 0.f;
#pragma unroll
    for (int s = 0; s < 4; s++) {
        float4 v = *(const float4*)&x[s*128 + l*4];
        xv[s*4+0]=v.x; xv[s*4+1]=v.y; xv[s*4+2]=v.z; xv[s*4+3]=v.w;
    }
#pragma unroll
    for (int t = 0; t < 16; t++) { sum += xv[t]; ssq += xv[t]*xv[t]; }
#pragma unroll
    for (int off = 16; off > 0; off >>= 1) {
        sum += __shfl_xor_sync(0xffffffffu, sum, off);
        ssq += __shfl_xor_sync(0xffffffffu, ssq, off);
    }
    float mean = sum * (1.f/DIM);
    float var  = ssq * (1.f/DIM) - mean*mean;
    float inv  = rsqrtf(var + 1e-5f);
    float* y = Y + (size_t)row * DIM;
    float qdot = 0.f;
#pragma unroll
    for (int s = 0; s < 4; s++) {
        int c = s*128 + l*4;
        float4 gv = *(const float4*)&g[c];
        float4 bv = *(const float4*)&b[c];
        float4 o;
        o.x = (xv[s*4+0]-mean)*inv*gv.x + bv.x;
        o.y = (xv[s*4+1]-mean)*inv*gv.y + bv.y;
        o.z = (xv[s*4+2]-mean)*inv*gv.z + bv.z;
        o.w = (xv[s*4+3]-mean)*inv*gv.w + bv.w;
        *(float4*)&y[c] = o;
        if (u) {
            float4 uv = *(const float4*)&u[c];
            qdot += o.x*uv.x + o.y*uv.y + o.z*uv.z + o.w*uv.w;
        }
    }
    if (qb) {
#pragma unroll
        for (int off = 16; off > 0; off >>= 1)
            qdot += __shfl_xor_sync(0xffffffffu, qdot, off);
        if (l == 0) qb[row] = qdot + *c0;
    }
}

// ---------------- fast small GEMM with f32x2 mainloop + double buffering ----------------
// C = act(A @ op(B) + bias) (+res).  BM=16, BN=64, BK=32, 128 threads.
// TRANSA: A is [K,M] row-major (used once for Wq^T @ Wk).
// TRANSB: B is [N,K] row-major (torch Linear weight).
#define GBM 16
#define GBN 64
#define GBK 32
#define GBM2 18   // padded u64 row stride (16B-aligned pairs)
#define GBN2 68   // padded float row stride (16B-aligned quads)

struct GPtrs { const float* A; const float* B; const float* bias; const float* res; float* C; };

template<bool TRANSA, bool TRANSB, int ACT, bool RESID>
__global__ __launch_bounds__(128) void gemm16(
    GPtrs p0, GPtrs p1, int lda, int ldb, int ldc, int K)
{
    __shared__ __align__(16) u64   As2[2][GBK*GBM2];
    __shared__ __align__(16) float Bs [2][GBK*GBN2];

    GPtrs P = (blockIdx.z == 0) ? p0 : p1;
    const float* __restrict__ A = P.A;
    const float* __restrict__ B = P.B;

    int tid = threadIdx.x;
    int m0 = blockIdx.x * GBM;
    int n0 = blockIdx.y * GBN;
    int tx = tid & 15;       // col group: 4 cols at tx*4
    int ty = tid >> 4;       // row pair:  rows ty*2, ty*2+1

    int a_m, a_k;
    if (TRANSA) { a_k = tid >> 2; a_m = (tid & 3) * 4; }
    else        { a_m = tid >> 3; a_k = (tid & 7) * 4; }

    float4 ar;
    float4 br[4];

    u64 acc00 = 0ull, acc01 = 0ull, acc10 = 0ull, acc11 = 0ull;
    int nT = K / GBK;

    // ---- tile load helpers (inlined) ----
    #define LOAD_A(t) do { \
        if (TRANSA) ar = *(const float4*)&A[(size_t)((t)*GBK + a_k)*lda + m0 + a_m]; \
        else        ar = *(const float4*)&A[(size_t)(m0 + a_m)*lda + (t)*GBK + a_k]; \
    } while (0)
    #define LOAD_B(t) do { \
        _Pragma("unroll") \
        for (int it = 0; it < 4; it++) { \
            int idx = tid + it*128; \
            if (TRANSB) { int n = idx >> 3, kq = (idx & 7)*4; \
                br[it] = *(const float4*)&B[(size_t)(n0+n)*ldb + (t)*GBK + kq]; } \
            else { int kk = idx >> 4, nq = (idx & 15)*4; \
                br[it] = *(const float4*)&B[(size_t)((t)*GBK+kk)*ldb + n0 + nq]; } \
        } \
    } while (0)
    #define STORE_AB(buf) do { \
        if (TRANSA) { \
            u64* dst = &As2[buf][a_k*GBM2 + a_m]; \
            dst[0] = pk2(ar.x, ar.x); dst[1] = pk2(ar.y, ar.y); \
            dst[2] = pk2(ar.z, ar.z); dst[3] = pk2(ar.w, ar.w); \
        } else { \
            As2[buf][(a_k+0)*GBM2 + a_m] = pk2(ar.x, ar.x); \
            As2[buf][(a_k+1)*GBM2 + a_m] = pk2(ar.y, ar.y); \
            As2[buf][(a_k+2)*GBM2 + a_m] = pk2(ar.z, ar.z); \
            As2[buf][(a_k+3)*GBM2 + a_m] = pk2(ar.w, ar.w); \
        } \
        _Pragma("unroll") \
        for (int it = 0; it < 4; it++) { \
            int idx = tid + it*128; \
            if (TRANSB) { int n = idx >> 3, kq = (idx & 7)*4; \
                Bs[buf][(kq+0)*GBN2 + n] = br[it].x; \
                Bs[buf][(kq+1)*GBN2 + n] = br[it].y; \
                Bs[buf][(kq+2)*GBN2 + n] = br[it].z; \
                Bs[buf][(kq+3)*GBN2 + n] = br[it].w; \
            } else { int kk = idx >> 4, nq = (idx & 15)*4; \
                *(float4*)&Bs[buf][kk*GBN2 + nq] = br[it]; } \
        } \
    } while (0)

    LOAD_A(0); LOAD_B(0);
    STORE_AB(0);
    __syncthreads();

    for (int t = 0; t < nT; t++) {
        int cur = t & 1;
        bool more = (t+1 < nT);
        if (more) { LOAD_A(t+1); LOAD_B(t+1); }
#pragma unroll
        for (int kk = 0; kk < GBK; kk++) {
            ulonglong2 aa = *(const ulonglong2*)&As2[cur][kk*GBM2 + ty*2];
            ulonglong2 bb = *(const ulonglong2*)&Bs [cur][kk*GBN2 + tx*4];
            acc00 = fma2_(aa.x, bb.x, acc00);
            acc01 = fma2_(aa.x, bb.y, acc01);
            acc10 = fma2_(aa.y, bb.x, acc10);
            acc11 = fma2_(aa.y, bb.y, acc11);
        }
        if (more) {
            __syncthreads();
            STORE_AB((t+1) & 1);
            __syncthreads();
        }
    }
    #undef LOAD_A
    #undef LOAD_B
    #undef STORE_AB

    float c00a,c00b,c01a,c01b,c10a,c10b,c11a,c11b;
    upk2(acc00, c00a, c00b); upk2(acc01, c01a, c01b);
    upk2(acc10, c10a, c10b); upk2(acc11, c11a, c11b);

    float4 bv = make_float4(0.f,0.f,0.f,0.f);
    if (P.bias) bv = *(const float4*)&P.bias[n0 + tx*4];

    float4 o0 = make_float4(c00a+bv.x, c00b+bv.y, c01a+bv.z, c01b+bv.w);
    float4 o1 = make_float4(c10a+bv.x, c10b+bv.y, c11a+bv.z, c11b+bv.w);
    if (ACT == 1) {
        o0.x=fmaxf(o0.x,0.f); o0.y=fmaxf(o0.y,0.f); o0.z=fmaxf(o0.z,0.f); o0.w=fmaxf(o0.w,0.f);
        o1.x=fmaxf(o1.x,0.f); o1.y=fmaxf(o1.y,0.f); o1.z=fmaxf(o1.z,0.f); o1.w=fmaxf(o1.w,0.f);
    }
    size_t r0 = (size_t)(m0 + ty*2)*ldc + n0 + tx*4;
    size_t r1 = r0 + ldc;
    if (RESID) {
        float4 q0 = *(const float4*)&P.res[r0];
        float4 q1 = *(const float4*)&P.res[r1];
        o0.x+=q0.x; o0.y+=q0.y; o0.z+=q0.z; o0.w+=q0.w;
        o1.x+=q1.x; o1.y+=q1.y; o1.z+=q1.z; o1.w+=q1.w;
    }
    *(float4*)&P.C[r0] = o0;
    *(float4*)&P.C[r1] = o1;
}

// ---------------- fused attention pass (packed f32x2) ----------------
__global__ __launch_bounds__(256) void attn_kernel(
    const float* __restrict__ X,
    const float* __restrict__ g_in, const float* __restrict__ be_in,
    const float* __restrict__ QK, const float* __restrict__ QB,
    float* __restrict__ Upart, float* __restrict__ Spart)
{
    __shared__ __align__(16) float qks[NSLOT][DIM];
    __shared__ __align__(16) float xs [NSLOT][DIM];
    __shared__ __align__(16) float gss[DIM];
    __shared__ __align__(16) float bss[DIM];
    __shared__ float ps [NSLOT][NSLOT];
    __shared__ float qbs[NSLOT];

    int b   = blockIdx.y;
    int ch  = blockIdx.x;
    int tid = threadIdx.x;
    int w = tid >> 5;
    int l = tid & 31;
    int cbase = l * 4;

    for (int i = tid*4; i < NSLOT*DIM; i += 1024)
        *(float4*)&qks[0][i] = *(const float4*)&QK[(size_t)b*NSLOT*DIM + i];
    if (tid < 128) {
        *(float4*)&gss[tid*4] = *(const float4*)&g_in[tid*4];
        *(float4*)&bss[tid*4] = *(const float4*)&be_in[tid*4];
    }
    if (tid < NSLOT) qbs[tid] = QB[b*NSLOT + tid];
    __syncthreads();

    u64 U2[8];
#pragma unroll
    for (int t = 0; t < 8; t++) U2[t] = 0ull;
    float Sl = 0.f;

    const float scale = 0.04419417382415922f;   // 512^-0.5
    int j0 = ch * TJ;

    for (int gidx = 0; gidx < TJ/8; gidx++) {
        // ---- phase 1: warp w owns token j ----
        int j = j0 + gidx*8 + w;
        const float* xrow = X + ((size_t)b*NTOK + j)*DIM;
        u64 xv[8];
        u64 sum2 = 0ull, ssq2 = 0ull;
#pragma unroll
        for (int s = 0; s < 4; s++) {
            ulonglong2 t2 = *(const ulonglong2*)&xrow[s*128 + cbase];
            xv[2*s] = t2.x; xv[2*s+1] = t2.y;
            sum2 = add2_(sum2, t2.x); sum2 = add2_(sum2, t2.y);
            ssq2 = fma2_(t2.x, t2.x, ssq2); ssq2 = fma2_(t2.y, t2.y, ssq2);
        }
        float sa, sb, qa, qc;
        upk2(sum2, sa, sb); upk2(ssq2, qa, qc);
        float sum = sa + sb, ssq = qa + qc;
#pragma unroll
        for (int off = 16; off > 0; off >>= 1) {
            sum += __shfl_xor_sync(0xffffffffu, sum, off);
            ssq += __shfl_xor_sync(0xffffffffu, ssq, off);
        }
        float mean = sum * (1.f/DIM);
        float var  = ssq * (1.f/DIM) - mean*mean;
        float inv  = rsqrtf(var + 1e-5f);
        u64 inv2 = pk2(inv, inv);
        u64 nm2  = pk2(-mean, -mean);

        u64 acc2[8];
#pragma unroll
        for (int i = 0; i < 8; i++) acc2[i] = 0ull;
#pragma unroll
        for (int s = 0; s < 4; s++) {
            int c = s*128 + cbase;
            ulonglong2 g2 = *(const ulonglong2*)&gss[c];
            ulonglong2 b2 = *(const ulonglong2*)&bss[c];
            u64 gi0 = mul2_(g2.x, inv2);
            u64 gi1 = mul2_(g2.y, inv2);
            u64 k0  = fma2_(nm2, gi0, b2.x);
            u64 k1  = fma2_(nm2, gi1, b2.y);
            u64 xa  = fma2_(xv[2*s],   gi0, k0);
            u64 xb  = fma2_(xv[2*s+1], gi1, k1);
            *(ulonglong2*)&xs[w][c] = make_ulonglong2(xa, xb);
#pragma unroll
            for (int i = 0; i < 8; i++) {
                ulonglong2 q2 = *(const ulonglong2*)&qks[i][c];
                acc2[i] = fma2_(q2.x, xa, acc2[i]);
                acc2[i] = fma2_(q2.y, xb, acc2[i]);
            }
        }
        float acc[8];
#pragma unroll
        for (int i = 0; i < 8; i++) { float a0,a1; upk2(acc2[i], a0, a1); acc[i] = a0 + a1; }
#pragma unroll
        for (int off = 16; off > 0; off >>= 1) {
#pragma unroll
            for (int i = 0; i < 8; i++)
                acc[i] += __shfl_xor_sync(0xffffffffu, acc[i], off);
        }
        float mx = -1e30f;
#pragma unroll
        for (int i = 0; i < 8; i++) {
            acc[i] = (acc[i] + qbs[i]) * scale;
            mx = fmaxf(mx, acc[i]);
        }
        float se = 0.f;
#pragma unroll
        for (int i = 0; i < 8; i++) { acc[i] = expf(acc[i]-mx); se += acc[i]; }
        float rse = 1.f/se;
        if (l < 8) ps[w][l] = acc[l]*rse + 1e-8f;
        __syncthreads();

        // ---- phase 2: warp w owns slot w ----
#pragma unroll
        for (int t = 0; t < 8; t++) {
            float pt = ps[t][w];
            Sl += pt;
            u64 pt2 = pk2(pt, pt);
#pragma unroll
            for (int s = 0; s < 4; s++) {
                ulonglong2 x2 = *(const ulonglong2*)&xs[t][s*128 + cbase];
                U2[2*s]   = fma2_(pt2, x2.x, U2[2*s]);
                U2[2*s+1] = fma2_(pt2, x2.y, U2[2*s+1]);
            }
        }
        __syncthreads();
    }

    float* up = Upart + (((size_t)b*CHUNKS + ch)*NSLOT + w)*DIM;
#pragma unroll
    for (int s = 0; s < 4; s++)
        *(ulonglong2*)&up[s*128 + cbase] = make_ulonglong2(U2[2*s], U2[2*s+1]);
    if (l == 0) Spart[(b*CHUNKS + ch)*NSLOT + w] = Sl;
}

// ---------------- reduce partials ----------------
__global__ void finish_kernel(const float* __restrict__ Upart,
                              const float* __restrict__ Spart,
                              float* __restrict__ Upre)
{
    int bi = blockIdx.x;            // b*8 + i
    int b = bi >> 3, i = bi & 7;
    int tid = threadIdx.x;          // 128
    __shared__ float ssum_s;
    if (tid < 32) {
        float s = Spart[(b*CHUNKS + tid)*NSLOT + i];
#pragma unroll
        for (int off = 16; off > 0; off >>= 1) s += __shfl_xor_sync(0xffffffffu, s, off);
        if (tid == 0) ssum_s = s;
    }
    __syncthreads();
    float rs = 1.f / ssum_s;
    int c = tid * 4;
    float4 acc = make_float4(0.f,0.f,0.f,0.f);
    for (int chn = 0; chn < CHUNKS; chn++) {
        float4 v = *(const float4*)&Upart[(((size_t)b*CHUNKS + chn)*NSLOT + i)*DIM + c];
        acc.x += v.x; acc.y += v.y; acc.z += v.z; acc.w += v.w;
    }
    acc.x*=rs; acc.y*=rs; acc.z*=rs; acc.w*=rs;
    *(float4*)&Upre[(size_t)bi*DIM + c] = acc;
}

// ---------------- GRU elementwise ----------------
__global__ void gru_kernel(const float* __restrict__ gx, const float* __restrict__ gh,
                           float* __restrict__ slots)
{
    int idx = blockIdx.x * blockDim.x + threadIdx.x;
    if (idx >= ROWS*DIM) return;
    int m = idx >> 9;
    int c = idx & (DIM-1);
    const float* gxm = gx + (size_t)m*3*DIM;
    const float* ghm = gh + (size_t)m*3*DIM;
    float r = 1.f/(1.f + expf(-(gxm[c]       + ghm[c])));
    float z = 1.f/(1.f + expf(-(gxm[DIM+c]   + ghm[DIM+c])));
    float n = tanhf(gxm[2*DIM+c] + r*ghm[2*DIM+c]);
    float h = slots[idx];
    slots[idx] = (1.f - z)*n + z*h;
}

// ---------------- host orchestration ----------------
extern "C" void kernel_launch(void* const* d_in, const int* in_sizes, int n_in,
                              void* d_out, int out_size)
{
    const float* inputs = (const float*)d_in[0];
    const float* noise  = (const float*)d_in[1];
    const float* mu     = (const float*)d_in[2];
    const float* sg     = (const float*)d_in[3];
    const float* Wq = (const float*)d_in[4];
    const float* bq = (const float*)d_in[5];
    const float* Wk = (const float*)d_in[6];
    const float* bk = (const float*)d_in[7];
    const float* Wv = (const float*)d_in[8];
    const float* bv = (const float*)d_in[9];
    const float* W_ih = (const float*)d_in[10];
    const float* b_ih = (const float*)d_in[11];
    const float* W_hh = (const float*)d_in[12];
    const float* b_hh = (const float*)d_in[13];
    const float* W1 = (const float*)d_in[14];
    const float* b1 = (const float*)d_in[15];
    const float* W2 = (const float*)d_in[16];
    const float* b2 = (const float*)d_in[17];
    const float* gin  = (const float*)d_in[18];
    const float* bein = (const float*)d_in[19];
    const float* gsl  = (const float*)d_in[20];
    const float* besl = (const float*)d_in[21];
    const float* gff  = (const float*)d_in[22];
    const float* beff = (const float*)d_in[23];

    float* slots = (float*)d_out;

    void* p;
    cudaGetSymbolAddress(&p, g_qn);    float* qn    = (float*)p;
    cudaGetSymbolAddress(&p, g_qk);    float* qk    = (float*)p;
    cudaGetSymbolAddress(&p, g_qb);    float* qb    = (float*)p;
    cudaGetSymbolAddress(&p, g_Mqk);   float* Mqk   = (float*)p;
    cudaGetSymbolAddress(&p, g_rqk);   float* rqk   = (float*)p;
    cudaGetSymbolAddress(&p, g_u);     float* uvec  = (float*)p;
    cudaGetSymbolAddress(&p, g_c0);    float* c0    = (float*)p;
    cudaGetSymbolAddress(&p, g_upart); float* upart = (float*)p;
    cudaGetSymbolAddress(&p, g_spart); float* spart = (float*)p;
    cudaGetSymbolAddress(&p, g_upre);  float* upre  = (float*)p;
    cudaGetSymbolAddress(&p, g_upd);   float* upd   = (float*)p;
    cudaGetSymbolAddress(&p, g_gx);    float* gx    = (float*)p;
    cudaGetSymbolAddress(&p, g_gh);    float* gh    = (float*)p;
    cudaGetSymbolAddress(&p, g_y);     float* ybuf  = (float*)p;
    cudaGetSymbolAddress(&p, g_h1);    float* h1    = (float*)p;

    init_slots_kernel<<<(ROWS*DIM + 255)/256, 256>>>(noise, mu, sg, slots);
    precompute_vecs<<<9, 128>>>(Wq, Wk, bq, bk, rqk, uvec, c0);

    // Mqk = Wq^T @ Wk  [512,512]
    {
        GPtrs a{Wq, Wk, nullptr, nullptr, Mqk};
        gemm16<true,false,0,false><<<dim3(DIM/GBM, DIM/GBN, 1), 128>>>(a, a, DIM, DIM, DIM, DIM);
    }

    for (int it = 0; it < 3; it++) {
        // LN(slots) (+ fused qb = qn.u + c0)
        ln_rows_kernel<<<32, 256>>>(slots, gsl, besl, qn, uvec, qb, c0);
        // qk = qn @ Mqk + rqk
        {
            GPtrs a{qn, Mqk, rqk, nullptr, qk};
            gemm16<false,false,0,false><<<dim3(ROWS/GBM, DIM/GBN, 1), 128>>>(a, a, DIM, DIM, DIM, DIM);
        }
        // fused attention streaming pass
        attn_kernel<<<dim3(CHUNKS, BATCH), 256>>>(inputs, gin, bein, qk, qb, upart, spart);
        finish_kernel<<<ROWS, 128>>>(upart, spart, upre);
        // updates = Upre @ Wv^T + bv
        {
            GPtrs a{upre, Wv, bv, nullptr, upd};
            gemm16<false,true,0,false><<<dim3(ROWS/GBM, DIM/GBN, 1), 128>>>(a, a, DIM, DIM, DIM, DIM);
        }
        // GRU gates: gx = upd @ W_ih^T + b_ih ; gh = slots @ W_hh^T + b_hh  (batched)
        {
            GPtrs a{upd,   W_ih, b_ih, nullptr, gx};
            GPtrs b{slots, W_hh, b_hh, nullptr, gh};
            gemm16<false,true,0,false><<<dim3(ROWS/GBM, (3*DIM)/GBN, 2), 128>>>(a, b, DIM, DIM, 3*DIM, DIM);
        }
        gru_kernel<<<(ROWS*DIM + 255)/256, 256>>>(gx, gh, slots);
        // MLP residual
        ln_rows_kernel<<<32, 256>>>(slots, gff, beff, ybuf, nullptr, nullptr, nullptr);
        {
            GPtrs a{ybuf, W1, b1, nullptr, h1};
            gemm16<false,true,1,false><<<dim3(ROWS/GBM, DIM/GBN, 1), 128>>>(a, a, DIM, DIM, DIM, DIM);
        }
        {
            GPtrs a{h1, W2, b2, slots, slots};
            gemm16<false,true,0,true><<<dim3(ROWS/GBM, DIM/GBN, 1), 128>>>(a, a, DIM, DIM, DIM, DIM);
        }
    }
}

// round 11
// speedup vs baseline: 1.1740x; 1.0072x over previous
#include <cuda_runtime.h>
#include <math.h>

#define BATCH 32
#define NTOK  4096
#define NSLOT 8
#define DIM   512
#define CHUNKS 32
#define TJ    128
#define ROWS  256

typedef unsigned long long u64;

// ---------------- packed f32x2 helpers ----------------
__device__ __forceinline__ u64 pk2(float lo, float hi) {
    u64 r; asm("mov.b64 %0, {%1, %2};" : "=l"(r) : "f"(lo), "f"(hi)); return r;
}
__device__ __forceinline__ void upk2(u64 v, float& a, float& b) {
    asm("mov.b64 {%0, %1}, %2;" : "=f"(a), "=f"(b) : "l"(v));
}
__device__ __forceinline__ u64 fma2_(u64 a, u64 b, u64 c) {
    u64 d; asm("fma.rn.f32x2 %0, %1, %2, %3;" : "=l"(d) : "l"(a), "l"(b), "l"(c)); return d;
}
__device__ __forceinline__ u64 add2_(u64 a, u64 b) {
    u64 d; asm("add.rn.f32x2 %0, %1, %2;" : "=l"(d) : "l"(a), "l"(b)); return d;
}
__device__ __forceinline__ u64 mul2_(u64 a, u64 b) {
    u64 d; asm("mul.rn.f32x2 %0, %1, %2;" : "=l"(d) : "l"(a), "l"(b)); return d;
}

// ---------------- device scratch ----------------
__device__ float g_qn   [ROWS*DIM];
__device__ float g_qk   [ROWS*DIM];
__device__ float g_qb   [ROWS];
__device__ float g_Mqk  [DIM*DIM];
__device__ float g_rqk  [DIM];
__device__ float g_u    [DIM];
__device__ float g_c0   [1];
__device__ float g_upart[BATCH*CHUNKS*NSLOT*DIM];
__device__ float g_spart[BATCH*CHUNKS*NSLOT];
__device__ float g_upre [ROWS*DIM];
__device__ float g_upd  [ROWS*DIM];
__device__ float g_gx   [ROWS*3*DIM];
__device__ float g_gh   [ROWS*3*DIM];
__device__ float g_y    [ROWS*DIM];
__device__ float g_h1   [ROWS*DIM];

// ---------------- slot init ----------------
__global__ void init_slots_kernel(const float* __restrict__ noise,
                                  const float* __restrict__ mu,
                                  const float* __restrict__ sg,
                                  float* __restrict__ slots)
{
    int idx = blockIdx.x * blockDim.x + threadIdx.x;
    if (idx >= ROWS*DIM) return;
    int c = idx & (DIM-1);
    slots[idx] = mu[c] + fabsf(sg[c]) * noise[idx];
}

// ---------------- one-time vector precompute ----------------
// rqk[f] = sum_d bq[d]*Wk[d,f];  u[e] = sum_d Wq[d,e]*bk[d];  c0 = bq.bk
__global__ void precompute_vecs(const float* __restrict__ Wq, const float* __restrict__ Wk,
                                const float* __restrict__ bq, const float* __restrict__ bk,
                                float* __restrict__ rqk, float* __restrict__ uvec,
                                float* __restrict__ c0)
{
    int bid = blockIdx.x;
    int tid = threadIdx.x;
    if (bid < 4) {
        int f = bid*128 + tid;
        float acc = 0.f;
#pragma unroll 8
        for (int d = 0; d < DIM; d++) acc += __ldg(&bq[d]) * Wk[(size_t)d*DIM + f];
        rqk[f] = acc;
    } else if (bid < 8) {
        int e = (bid-4)*128 + tid;
        float acc = 0.f;
#pragma unroll 8
        for (int d = 0; d < DIM; d++) acc += __ldg(&bk[d]) * Wq[(size_t)d*DIM + e];
        uvec[e] = acc;
    } else {
        __shared__ float red[128];
        float acc = 0.f;
        for (int d = tid; d < DIM; d += 128) acc += bq[d]*bk[d];
        red[tid] = acc; __syncthreads();
        for (int s = 64; s > 0; s >>= 1) { if (tid < s) red[tid] += red[tid+s]; __syncthreads(); }
        if (tid == 0) *c0 = red[0];
    }
}

// ---------------- LayerNorm (+ optional fused qb = y.u + c0) ----------------
__global__ void ln_rows_kernel(const float* __restrict__ X,
                               const float* __restrict__ g,
                               const float* __restrict__ b,
                               float* __restrict__ Y,
                               const float* __restrict__ u,
                               float* __restrict__ qb,
                               const float* __restrict__ c0)
{
    int row = blockIdx.x * 8 + (threadIdx.x >> 5);
    int l   = threadIdx.x & 31;
    const float* x = X + (size_t)row * DIM;
    float xv[16];
    float sum = 0.f, ssq = 0.f;
#pragma unroll
    for (int s = 0; s < 4; s++) {
        float4 v = *(const float4*)&x[s*128 + l*4];
        xv[s*4+0]=v.x; xv[s*4+1]=v.y; xv[s*4+2]=v.z; xv[s*4+3]=v.w;
    }
#pragma unroll
    for (int t = 0; t < 16; t++) { sum += xv[t]; ssq += xv[t]*xv[t]; }
#pragma unroll
    for (int off = 16; off > 0; off >>= 1) {
        sum += __shfl_xor_sync(0xffffffffu, sum, off);
        ssq += __shfl_xor_sync(0xffffffffu, ssq, off);
    }
    float mean = sum * (1.f/DIM);
    float var  = ssq * (1.f/DIM) - mean*mean;
    float inv  = rsqrtf(var + 1e-5f);
    float* y = Y + (size_t)row * DIM;
    float qdot = 0.f;
#pragma unroll
    for (int s = 0; s < 4; s++) {
        int c = s*128 + l*4;
        float4 gv = *(const float4*)&g[c];
        float4 bv = *(const float4*)&b[c];
        float4 o;
        o.x = (xv[s*4+0]-mean)*inv*gv.x + bv.x;
        o.y = (xv[s*4+1]-mean)*inv*gv.y + bv.y;
        o.z = (xv[s*4+2]-mean)*inv*gv.z + bv.z;
        o.w = (xv[s*4+3]-mean)*inv*gv.w + bv.w;
        *(float4*)&y[c] = o;
        if (u) {
            float4 uv = *(const float4*)&u[c];
            qdot += o.x*uv.x + o.y*uv.y + o.z*uv.z + o.w*uv.w;
        }
    }
    if (qb) {
#pragma unroll
        for (int off = 16; off > 0; off >>= 1)
            qdot += __shfl_xor_sync(0xffffffffu, qdot, off);
        if (l == 0) qb[row] = qdot + *c0;
    }
}

// ---------------- fast small GEMM with f32x2 mainloop + double buffering ----------------
// C = act(A @ op(B) + bias) (+res).  BM=16, BN=64, BK=32, 128 threads.
// TRANSA: A is [K,M] row-major (used once for Wq^T @ Wk).
// TRANSB: B is [N,K] row-major (torch Linear weight).
#define GBM 16
#define GBN 64
#define GBK 32
#define GBM2 18   // padded u64 row stride (16B-aligned pairs)
#define GBN2 68   // padded float row stride (16B-aligned quads)

struct GPtrs { const float* A; const float* B; const float* bias; const float* res; float* C; };

template<bool TRANSA, bool TRANSB, int ACT, bool RESID>
__global__ __launch_bounds__(128) void gemm16(
    GPtrs p0, GPtrs p1, int lda, int ldb, int ldc, int K)
{
    __shared__ __align__(16) u64   As2[2][GBK*GBM2];
    __shared__ __align__(16) float Bs [2][GBK*GBN2];

    GPtrs P = (blockIdx.z == 0) ? p0 : p1;
    const float* __restrict__ A = P.A;
    const float* __restrict__ B = P.B;

    int tid = threadIdx.x;
    int m0 = blockIdx.x * GBM;
    int n0 = blockIdx.y * GBN;
    int tx = tid & 15;       // col group: 4 cols at tx*4
    int ty = tid >> 4;       // row pair:  rows ty*2, ty*2+1

    int a_m, a_k;
    if (TRANSA) { a_k = tid >> 2; a_m = (tid & 3) * 4; }
    else        { a_m = tid >> 3; a_k = (tid & 7) * 4; }

    float4 ar;
    float4 br[4];

    u64 acc00 = 0ull, acc01 = 0ull, acc10 = 0ull, acc11 = 0ull;
    int nT = K / GBK;

    // ---- tile load helpers (inlined) ----
    #define LOAD_A(t) do { \
        if (TRANSA) ar = *(const float4*)&A[(size_t)((t)*GBK + a_k)*lda + m0 + a_m]; \
        else        ar = *(const float4*)&A[(size_t)(m0 + a_m)*lda + (t)*GBK + a_k]; \
    } while (0)
    #define LOAD_B(t) do { \
        _Pragma("unroll") \
        for (int it = 0; it < 4; it++) { \
            int idx = tid + it*128; \
            if (TRANSB) { int n = idx >> 3, kq = (idx & 7)*4; \
                br[it] = *(const float4*)&B[(size_t)(n0+n)*ldb + (t)*GBK + kq]; } \
            else { int kk = idx >> 4, nq = (idx & 15)*4; \
                br[it] = *(const float4*)&B[(size_t)((t)*GBK+kk)*ldb + n0 + nq]; } \
        } \
    } while (0)
    #define STORE_AB(buf) do { \
        if (TRANSA) { \
            u64* dst = &As2[buf][a_k*GBM2 + a_m]; \
            dst[0] = pk2(ar.x, ar.x); dst[1] = pk2(ar.y, ar.y); \
            dst[2] = pk2(ar.z, ar.z); dst[3] = pk2(ar.w, ar.w); \
        } else { \
            As2[buf][(a_k+0)*GBM2 + a_m] = pk2(ar.x, ar.x); \
            As2[buf][(a_k+1)*GBM2 + a_m] = pk2(ar.y, ar.y); \
            As2[buf][(a_k+2)*GBM2 + a_m] = pk2(ar.z, ar.z); \
            As2[buf][(a_k+3)*GBM2 + a_m] = pk2(ar.w, ar.w); \
        } \
        _Pragma("unroll") \
        for (int it = 0; it < 4; it++) { \
            int idx = tid + it*128; \
            if (TRANSB) { int n = idx >> 3, kq = (idx & 7)*4; \
                Bs[buf][(kq+0)*GBN2 + n] = br[it].x; \
                Bs[buf][(kq+1)*GBN2 + n] = br[it].y; \
                Bs[buf][(kq+2)*GBN2 + n] = br[it].z; \
                Bs[buf][(kq+3)*GBN2 + n] = br[it].w; \
            } else { int kk = idx >> 4, nq = (idx & 15)*4; \
                *(float4*)&Bs[buf][kk*GBN2 + nq] = br[it]; } \
        } \
    } while (0)

    LOAD_A(0); LOAD_B(0);
    STORE_AB(0);
    __syncthreads();

    for (int t = 0; t < nT; t++) {
        int cur = t & 1;
        bool more = (t+1 < nT);
        if (more) { LOAD_A(t+1); LOAD_B(t+1); }
#pragma unroll
        for (int kk = 0; kk < GBK; kk++) {
            ulonglong2 aa = *(const ulonglong2*)&As2[cur][kk*GBM2 + ty*2];
            ulonglong2 bb = *(const ulonglong2*)&Bs [cur][kk*GBN2 + tx*4];
            acc00 = fma2_(aa.x, bb.x, acc00);
            acc01 = fma2_(aa.x, bb.y, acc01);
            acc10 = fma2_(aa.y, bb.x, acc10);
            acc11 = fma2_(aa.y, bb.y, acc11);
        }
        if (more) {
            __syncthreads();
            STORE_AB((t+1) & 1);
            __syncthreads();
        }
    }
    #undef LOAD_A
    #undef LOAD_B
    #undef STORE_AB

    float c00a,c00b,c01a,c01b,c10a,c10b,c11a,c11b;
    upk2(acc00, c00a, c00b); upk2(acc01, c01a, c01b);
    upk2(acc10, c10a, c10b); upk2(acc11, c11a, c11b);

    float4 bv = make_float4(0.f,0.f,0.f,0.f);
    if (P.bias) bv = *(const float4*)&P.bias[n0 + tx*4];

    float4 o0 = make_float4(c00a+bv.x, c00b+bv.y, c01a+bv.z, c01b+bv.w);
    float4 o1 = make_float4(c10a+bv.x, c10b+bv.y, c11a+bv.z, c11b+bv.w);
    if (ACT == 1) {
        o0.x=fmaxf(o0.x,0.f); o0.y=fmaxf(o0.y,0.f); o0.z=fmaxf(o0.z,0.f); o0.w=fmaxf(o0.w,0.f);
        o1.x=fmaxf(o1.x,0.f); o1.y=fmaxf(o1.y,0.f); o1.z=fmaxf(o1.z,0.f); o1.w=fmaxf(o1.w,0.f);
    }
    size_t r0 = (size_t)(m0 + ty*2)*ldc + n0 + tx*4;
    size_t r1 = r0 + ldc;
    if (RESID) {
        float4 q0 = *(const float4*)&P.res[r0];
        float4 q1 = *(const float4*)&P.res[r1];
        o0.x+=q0.x; o0.y+=q0.y; o0.z+=q0.z; o0.w+=q0.w;
        o1.x+=q1.x; o1.y+=q1.y; o1.z+=q1.z; o1.w+=q1.w;
    }
    *(float4*)&P.C[r0] = o0;
    *(float4*)&P.C[r1] = o1;
}

// ---------------- fused attention pass (packed f32x2) ----------------
__global__ __launch_bounds__(256) void attn_kernel(
    const float* __restrict__ X,
    const float* __restrict__ g_in, const float* __restrict__ be_in,
    const float* __restrict__ QK, const float* __restrict__ QB,
    float* __restrict__ Upart, float* __restrict__ Spart)
{
    __shared__ __align__(16) float qks[NSLOT][DIM];
    __shared__ __align__(16) float xs [NSLOT][DIM];
    __shared__ __align__(16) float gss[DIM];
    __shared__ __align__(16) float bss[DIM];
    __shared__ float ps [NSLOT][NSLOT];
    __shared__ float qbs[NSLOT];

    int b   = blockIdx.y;
    int ch  = blockIdx.x;
    int tid = threadIdx.x;
    int w = tid >> 5;
    int l = tid & 31;
    int cbase = l * 4;

    for (int i = tid*4; i < NSLOT*DIM; i += 1024)
        *(float4*)&qks[0][i] = *(const float4*)&QK[(size_t)b*NSLOT*DIM + i];
    if (tid < 128) {
        *(float4*)&gss[tid*4] = *(const float4*)&g_in[tid*4];
        *(float4*)&bss[tid*4] = *(const float4*)&be_in[tid*4];
    }
    if (tid < NSLOT) qbs[tid] = QB[b*NSLOT + tid];
    __syncthreads();

    u64 U2[8];
#pragma unroll
    for (int t = 0; t < 8; t++) U2[t] = 0ull;
    float Sl = 0.f;

    const float scale = 0.04419417382415922f;   // 512^-0.5
    int j0 = ch * TJ;

    for (int gidx = 0; gidx < TJ/8; gidx++) {
        // ---- phase 1: warp w owns token j ----
        int j = j0 + gidx*8 + w;
        const float* xrow = X + ((size_t)b*NTOK + j)*DIM;
        u64 xv[8];
        u64 sum2 = 0ull, ssq2 = 0ull;
#pragma unroll
        for (int s = 0; s < 4; s++) {
            ulonglong2 t2 = *(const ulonglong2*)&xrow[s*128 + cbase];
            xv[2*s] = t2.x; xv[2*s+1] = t2.y;
            sum2 = add2_(sum2, t2.x); sum2 = add2_(sum2, t2.y);
            ssq2 = fma2_(t2.x, t2.x, ssq2); ssq2 = fma2_(t2.y, t2.y, ssq2);
        }
        float sa, sb, qa, qc;
        upk2(sum2, sa, sb); upk2(ssq2, qa, qc);
        float sum = sa + sb, ssq = qa + qc;
#pragma unroll
        for (int off = 16; off > 0; off >>= 1) {
            sum += __shfl_xor_sync(0xffffffffu, sum, off);
            ssq += __shfl_xor_sync(0xffffffffu, ssq, off);
        }
        float mean = sum * (1.f/DIM);
        float var  = ssq * (1.f/DIM) - mean*mean;
        float inv  = rsqrtf(var + 1e-5f);
        u64 inv2 = pk2(inv, inv);
        u64 nm2  = pk2(-mean, -mean);

        u64 acc2[8];
#pragma unroll
        for (int i = 0; i < 8; i++) acc2[i] = 0ull;
#pragma unroll
        for (int s = 0; s < 4; s++) {
            int c = s*128 + cbase;
            ulonglong2 g2 = *(const ulonglong2*)&gss[c];
            ulonglong2 b2 = *(const ulonglong2*)&bss[c];
            u64 gi0 = mul2_(g2.x, inv2);
            u64 gi1 = mul2_(g2.y, inv2);
            u64 k0  = fma2_(nm2, gi0, b2.x);
            u64 k1  = fma2_(nm2, gi1, b2.y);
            u64 xa  = fma2_(xv[2*s],   gi0, k0);
            u64 xb  = fma2_(xv[2*s+1], gi1, k1);
            *(ulonglong2*)&xs[w][c] = make_ulonglong2(xa, xb);
#pragma unroll
            for (int i = 0; i < 8; i++) {
                ulonglong2 q2 = *(const ulonglong2*)&qks[i][c];
                acc2[i] = fma2_(q2.x, xa, acc2[i]);
                acc2[i] = fma2_(q2.y, xb, acc2[i]);
            }
        }
        float acc[8];
#pragma unroll
        for (int i = 0; i < 8; i++) { float a0,a1; upk2(acc2[i], a0, a1); acc[i] = a0 + a1; }
#pragma unroll
        for (int off = 16; off > 0; off >>= 1) {
#pragma unroll
            for (int i = 0; i < 8; i++)
                acc[i] += __shfl_xor_sync(0xffffffffu, acc[i], off);
        }
        float mx = -1e30f;
#pragma unroll
        for (int i = 0; i < 8; i++) {
            acc[i] = (acc[i] + qbs[i]) * scale;
            mx = fmaxf(mx, acc[i]);
        }
        float se = 0.f;
#pragma unroll
        for (int i = 0; i < 8; i++) { acc[i] = expf(acc[i]-mx); se += acc[i]; }
        float rse = 1.f/se;
        if (l < 8) ps[w][l] = acc[l]*rse + 1e-8f;
        __syncthreads();

        // ---- phase 2: warp w owns slot w ----
#pragma unroll
        for (int t = 0; t < 8; t++) {
            float pt = ps[t][w];
            Sl += pt;
            u64 pt2 = pk2(pt, pt);
#pragma unroll
            for (int s = 0; s < 4; s++) {
                ulonglong2 x2 = *(const ulonglong2*)&xs[t][s*128 + cbase];
                U2[2*s]   = fma2_(pt2, x2.x, U2[2*s]);
                U2[2*s+1] = fma2_(pt2, x2.y, U2[2*s+1]);
            }
        }
        __syncthreads();
    }

    float* up = Upart + (((size_t)b*CHUNKS + ch)*NSLOT + w)*DIM;
#pragma unroll
    for (int s = 0; s < 4; s++)
        *(ulonglong2*)&up[s*128 + cbase] = make_ulonglong2(U2[2*s], U2[2*s+1]);
    if (l == 0) Spart[(b*CHUNKS + ch)*NSLOT + w] = Sl;
}

// ---------------- reduce partials ----------------
__global__ void finish_kernel(const float* __restrict__ Upart,
                              const float* __restrict__ Spart,
                              float* __restrict__ Upre)
{
    int bi = blockIdx.x;            // b*8 + i
    int b = bi >> 3, i = bi & 7;
    int tid = threadIdx.x;          // 128
    __shared__ float ssum_s;
    if (tid < 32) {
        float s = Spart[(b*CHUNKS + tid)*NSLOT + i];
#pragma unroll
        for (int off = 16; off > 0; off >>= 1) s += __shfl_xor_sync(0xffffffffu, s, off);
        if (tid == 0) ssum_s = s;
    }
    __syncthreads();
    float rs = 1.f / ssum_s;
    int c = tid * 4;
    float4 acc = make_float4(0.f,0.f,0.f,0.f);
    for (int chn = 0; chn < CHUNKS; chn++) {
        float4 v = *(const float4*)&Upart[(((size_t)b*CHUNKS + chn)*NSLOT + i)*DIM + c];
        acc.x += v.x; acc.y += v.y; acc.z += v.z; acc.w += v.w;
    }
    acc.x*=rs; acc.y*=rs; acc.z*=rs; acc.w*=rs;
    *(float4*)&Upre[(size_t)bi*DIM + c] = acc;
}

// ---------------- GRU elementwise ----------------
__global__ void gru_kernel(const float* __restrict__ gx, const float* __restrict__ gh,
                           float* __restrict__ slots)
{
    int idx = blockIdx.x * blockDim.x + threadIdx.x;
    if (idx >= ROWS*DIM) return;
    int m = idx >> 9;
    int c = idx & (DIM-1);
    const float* gxm = gx + (size_t)m*3*DIM;
    const float* ghm = gh + (size_t)m*3*DIM;
    float r = 1.f/(1.f + expf(-(gxm[c]       + ghm[c])));
    float z = 1.f/(1.f + expf(-(gxm[DIM+c]   + ghm[DIM+c])));
    float n = tanhf(gxm[2*DIM+c] + r*ghm[2*DIM+c]);
    float h = slots[idx];
    slots[idx] = (1.f - z)*n + z*h;
}

// ---------------- host orchestration ----------------
extern "C" void kernel_launch(void* const* d_in, const int* in_sizes, int n_in,
                              void* d_out, int out_size)
{
    const float* inputs = (const float*)d_in[0];
    const float* noise  = (const float*)d_in[1];
    const float* mu     = (const float*)d_in[2];
    const float* sg     = (const float*)d_in[3];
    const float* Wq = (const float*)d_in[4];
    const float* bq = (const float*)d_in[5];
    const float* Wk = (const float*)d_in[6];
    const float* bk = (const float*)d_in[7];
    const float* Wv = (const float*)d_in[8];
    const float* bv = (const float*)d_in[9];
    const float* W_ih = (const float*)d_in[10];
    const float* b_ih = (const float*)d_in[11];
    const float* W_hh = (const float*)d_in[12];
    const float* b_hh = (const float*)d_in[13];
    const float* W1 = (const float*)d_in[14];
    const float* b1 = (const float*)d_in[15];
    const float* W2 = (const float*)d_in[16];
    const float* b2 = (const float*)d_in[17];
    const float* gin  = (const float*)d_in[18];
    const float* bein = (const float*)d_in[19];
    const float* gsl  = (const float*)d_in[20];
    const float* besl = (const float*)d_in[21];
    const float* gff  = (const float*)d_in[22];
    const float* beff = (const float*)d_in[23];

    float* slots = (float*)d_out;

    void* p;
    cudaGetSymbolAddress(&p, g_qn);    float* qn    = (float*)p;
    cudaGetSymbolAddress(&p, g_qk);    float* qk    = (float*)p;
    cudaGetSymbolAddress(&p, g_qb);    float* qb    = (float*)p;
    cudaGetSymbolAddress(&p, g_Mqk);   float* Mqk   = (float*)p;
    cudaGetSymbolAddress(&p, g_rqk);   float* rqk   = (float*)p;
    cudaGetSymbolAddress(&p, g_u);     float* uvec  = (float*)p;
    cudaGetSymbolAddress(&p, g_c0);    float* c0    = (float*)p;
    cudaGetSymbolAddress(&p, g_upart); float* upart = (float*)p;
    cudaGetSymbolAddress(&p, g_spart); float* spart = (float*)p;
    cudaGetSymbolAddress(&p, g_upre);  float* upre  = (float*)p;
    cudaGetSymbolAddress(&p, g_upd);   float* upd   = (float*)p;
    cudaGetSymbolAddress(&p, g_gx);    float* gx    = (float*)p;
    cudaGetSymbolAddress(&p, g_gh);    float* gh    = (float*)p;
    cudaGetSymbolAddress(&p, g_y);     float* ybuf  = (float*)p;
    cudaGetSymbolAddress(&p, g_h1);    float* h1    = (float*)p;

    init_slots_kernel<<<(ROWS*DIM + 255)/256, 256>>>(noise, mu, sg, slots);
    precompute_vecs<<<9, 128>>>(Wq, Wk, bq, bk, rqk, uvec, c0);

    // Mqk = Wq^T @ Wk  [512,512]
    {
        GPtrs a{Wq, Wk, nullptr, nullptr, Mqk};
        gemm16<true,false,0,false><<<dim3(DIM/GBM, DIM/GBN, 1), 128>>>(a, a, DIM, DIM, DIM, DIM);
    }

    for (int it = 0; it < 3; it++) {
        // LN(slots) (+ fused qb = qn.u + c0)
        ln_rows_kernel<<<32, 256>>>(slots, gsl, besl, qn, uvec, qb, c0);
        // qk = qn @ Mqk + rqk
        {
            GPtrs a{qn, Mqk, rqk, nullptr, qk};
            gemm16<false,false,0,false><<<dim3(ROWS/GBM, DIM/GBN, 1), 128>>>(a, a, DIM, DIM, DIM, DIM);
        }
        // fused attention streaming pass
        attn_kernel<<<dim3(CHUNKS, BATCH), 256>>>(inputs, gin, bein, qk, qb, upart, spart);
        finish_kernel<<<ROWS, 128>>>(upart, spart, upre);
        // updates = Upre @ Wv^T + bv
        {
            GPtrs a{upre, Wv, bv, nullptr, upd};
            gemm16<false,true,0,false><<<dim3(ROWS/GBM, DIM/GBN, 1), 128>>>(a, a, DIM, DIM, DIM, DIM);
        }
        // GRU gates: gx = upd @ W_ih^T + b_ih ; gh = slots @ W_hh^T + b_hh  (batched)
        {
            GPtrs a{upd,   W_ih, b_ih, nullptr, gx};
            GPtrs b{slots, W_hh, b_hh, nullptr, gh};
            gemm16<false,true,0,false><<<dim3(ROWS/GBM, (3*DIM)/GBN, 2), 128>>>(a, b, DIM, DIM, 3*DIM, DIM);
        }
        gru_kernel<<<(ROWS*DIM + 255)/256, 256>>>(gx, gh, slots);
        // MLP residual
        ln_rows_kernel<<<32, 256>>>(slots, gff, beff, ybuf, nullptr, nullptr, nullptr);
        {
            GPtrs a{ybuf, W1, b1, nullptr, h1};
            gemm16<false,true,1,false><<<dim3(ROWS/GBM, DIM/GBN, 1), 128>>>(a, a, DIM, DIM, DIM, DIM);
        }
        {
            GPtrs a{h1, W2, b2, slots, slots};
            gemm16<false,true,0,true><<<dim3(ROWS/GBM, DIM/GBN, 1), 128>>>(a, a, DIM, DIM, DIM, DIM);
        }
    }
}

// round 12
// speedup vs baseline: 1.3756x; 1.1717x over previous
#include <cuda_runtime.h>
#include <math.h>

#define BATCH 32
#define NTOK  4096
#define NSLOT 8
#define DIM   512
#define CH    32          // chunks per batch (attn)
#define CTOK  128         // tokens per chunk
#define GTOK  16          // tokens per group (2 per warp)
#define ROWS  256

typedef unsigned long long u64;

// ---------------- packed f32x2 helpers ----------------
__device__ __forceinline__ u64 pk2(float lo, float hi) {
    u64 r; asm("mov.b64 %0, {%1, %2};" : "=l"(r) : "f"(lo), "f"(hi)); return r;
}
__device__ __forceinline__ void upk2(u64 v, float& a, float& b) {
    asm("mov.b64 {%0, %1}, %2;" : "=f"(a), "=f"(b) : "l"(v));
}
__device__ __forceinline__ u64 fma2_(u64 a, u64 b, u64 c) {
    u64 d; asm("fma.rn.f32x2 %0, %1, %2, %3;" : "=l"(d) : "l"(a), "l"(b), "l"(c)); return d;
}
__device__ __forceinline__ u64 add2_(u64 a, u64 b) {
    u64 d; asm("add.rn.f32x2 %0, %1, %2;" : "=l"(d) : "l"(a), "l"(b)); return d;
}
__device__ __forceinline__ u64 mul2_(u64 a, u64 b) {
    u64 d; asm("mul.rn.f32x2 %0, %1, %2;" : "=l"(d) : "l"(a), "l"(b)); return d;
}

// ---------------- device scratch ----------------
__device__ float g_qk   [ROWS*DIM];
__device__ float g_qb   [ROWS];
__device__ float g_Mqk  [DIM*DIM];
__device__ float g_rqk  [DIM];
__device__ float g_u    [DIM];
__device__ float g_c0   [1];
__device__ float g_gu   [DIM];
__device__ float g_sc   [2];
__device__ float g_mq   [ROWS];
__device__ float g_rq   [ROWS];
__device__ float g_mf   [ROWS];
__device__ float g_rf   [ROWS];
__device__ float g_upart[BATCH*CH*NSLOT*DIM];
__device__ float g_spart[BATCH*CH*NSLOT];
__device__ float g_upre [ROWS*DIM];
__device__ float g_upd  [ROWS*DIM];
__device__ float g_gx   [ROWS*3*DIM];
__device__ float g_gh   [ROWS*3*DIM];
__device__ float g_h1   [ROWS*DIM];

// ---------------- slot init ----------------
__global__ void init_slots_kernel(const float* __restrict__ noise,
                                  const float* __restrict__ mu,
                                  const float* __restrict__ sg,
                                  float* __restrict__ slots)
{
    int idx = blockIdx.x * blockDim.x + threadIdx.x;
    if (idx >= ROWS*DIM) return;
    int c = idx & (DIM-1);
    slots[idx] = mu[c] + fabsf(sg[c]) * noise[idx];
}

// ---------------- one-time vector precompute ----------------
// rqk[f] = sum_d bq[d]*Wk[d,f];  u[e] = sum_d Wq[d,e]*bk[d];  c0 = bq.bk
__global__ void precompute_vecs(const float* __restrict__ Wq, const float* __restrict__ Wk,
                                const float* __restrict__ bq, const float* __restrict__ bk,
                                float* __restrict__ rqk, float* __restrict__ uvec,
                                float* __restrict__ c0)
{
    int bid = blockIdx.x;
    int tid = threadIdx.x;
    if (bid < 4) {
        int f = bid*128 + tid;
        float acc = 0.f;
#pragma unroll 8
        for (int d = 0; d < DIM; d++) acc += __ldg(&bq[d]) * Wk[(size_t)d*DIM + f];
        rqk[f] = acc;
    } else if (bid < 8) {
        int e = (bid-4)*128 + tid;
        float acc = 0.f;
#pragma unroll 8
        for (int d = 0; d < DIM; d++) acc += __ldg(&bk[d]) * Wq[(size_t)d*DIM + e];
        uvec[e] = acc;
    } else {
        __shared__ float red[128];
        float acc = 0.f;
        for (int d = tid; d < DIM; d += 128) acc += bq[d]*bk[d];
        red[tid] = acc; __syncthreads();
        for (int s = 64; s > 0; s >>= 1) { if (tid < s) red[tid] += red[tid+s]; __syncthreads(); }
        if (tid == 0) *c0 = red[0];
    }
}

// gu[c] = g_sl[c]*u[c];  sc[0] = sum gu;  sc[1] = sum be_sl*u + c0
__global__ void precompute2(const float* __restrict__ gsl, const float* __restrict__ besl,
                            const float* __restrict__ uvec, const float* __restrict__ c0,
                            float* __restrict__ gu, float* __restrict__ sc)
{
    __shared__ float r1[16], r2[16];
    int tid = threadIdx.x;  // 512
    float u = uvec[tid];
    float gv = gsl[tid]*u;
    gu[tid] = gv;
    float bv = besl[tid]*u;
#pragma unroll
    for (int off = 16; off > 0; off >>= 1) {
        gv += __shfl_xor_sync(0xffffffffu, gv, off);
        bv += __shfl_xor_sync(0xffffffffu, bv, off);
    }
    int w = tid >> 5;
    if ((tid & 31) == 0) { r1[w] = gv; r2[w] = bv; }
    __syncthreads();
    if (tid == 0) {
        float s1 = 0.f, s2 = 0.f;
        for (int i = 0; i < 16; i++) { s1 += r1[i]; s2 += r2[i]; }
        sc[0] = s1; sc[1] = s2 + *c0;
    }
}

// ---------------- per-row LN stats for slots (+ fused qb) ----------------
__global__ void stats_q_kernel(const float* __restrict__ slots,
                               const float* __restrict__ gu,
                               const float* __restrict__ sc,
                               float* __restrict__ meanq, float* __restrict__ rstdq,
                               float* __restrict__ qb)
{
    int row = blockIdx.x * 8 + (threadIdx.x >> 5);
    int l   = threadIdx.x & 31;
    const float* x = slots + (size_t)row * DIM;
    float sum = 0.f, ssq = 0.f, dgu = 0.f;
#pragma unroll
    for (int s = 0; s < 4; s++) {
        float4 v  = *(const float4*)&x[s*128 + l*4];
        float4 gv = *(const float4*)&gu[s*128 + l*4];
        sum += v.x + v.y + v.z + v.w;
        ssq += v.x*v.x + v.y*v.y + v.z*v.z + v.w*v.w;
        dgu += v.x*gv.x + v.y*gv.y + v.z*gv.z + v.w*gv.w;
    }
#pragma unroll
    for (int off = 16; off > 0; off >>= 1) {
        sum += __shfl_xor_sync(0xffffffffu, sum, off);
        ssq += __shfl_xor_sync(0xffffffffu, ssq, off);
        dgu += __shfl_xor_sync(0xffffffffu, dgu, off);
    }
    if (l == 0) {
        float mean = sum * (1.f/DIM);
        float var  = ssq * (1.f/DIM) - mean*mean;
        float r    = rsqrtf(var + 1e-5f);
        meanq[row] = mean;
        rstdq[row] = r;
        qb[row]    = r*(dgu - mean*sc[0]) + sc[1];
    }
}

// ---------------- per-row ff-LN stats for slots ----------------
__global__ void gru_ln_kernel(const float* __restrict__ gx, const float* __restrict__ gh,
                              float* __restrict__ slots,
                              float* __restrict__ meanf, float* __restrict__ rstdf)
{
    __shared__ float r1[4], r2[4];
    int row = blockIdx.x;
    int tid = threadIdx.x;      // 128
    int c = tid * 4;
    const float* gxm = gx + (size_t)row*3*DIM;
    const float* ghm = gh + (size_t)row*3*DIM;
    float4 xr = *(const float4*)&gxm[c];
    float4 xz = *(const float4*)&gxm[DIM + c];
    float4 xn = *(const float4*)&gxm[2*DIM + c];
    float4 hr = *(const float4*)&ghm[c];
    float4 hz = *(const float4*)&ghm[DIM + c];
    float4 hn = *(const float4*)&ghm[2*DIM + c];
    float4 h4 = *(const float4*)&slots[(size_t)row*DIM + c];
    float4 o;
    {
        float r = 1.f/(1.f + __expf(-(xr.x + hr.x)));
        float z = 1.f/(1.f + __expf(-(xz.x + hz.x)));
        float n = tanhf(xn.x + r*hn.x);
        o.x = (1.f - z)*n + z*h4.x;
    }
    {
        float r = 1.f/(1.f + __expf(-(xr.y + hr.y)));
        float z = 1.f/(1.f + __expf(-(xz.y + hz.y)));
        float n = tanhf(xn.y + r*hn.y);
        o.y = (1.f - z)*n + z*h4.y;
    }
    {
        float r = 1.f/(1.f + __expf(-(xr.z + hr.z)));
        float z = 1.f/(1.f + __expf(-(xz.z + hz.z)));
        float n = tanhf(xn.z + r*hn.z);
        o.z = (1.f - z)*n + z*h4.z;
    }
    {
        float r = 1.f/(1.f + __expf(-(xr.w + hr.w)));
        float z = 1.f/(1.f + __expf(-(xz.w + hz.w)));
        float n = tanhf(xn.w + r*hn.w);
        o.w = (1.f - z)*n + z*h4.w;
    }
    *(float4*)&slots[(size_t)row*DIM + c] = o;
    float sum = o.x + o.y + o.z + o.w;
    float ssq = o.x*o.x + o.y*o.y + o.z*o.z + o.w*o.w;
#pragma unroll
    for (int off = 16; off > 0; off >>= 1) {
        sum += __shfl_xor_sync(0xffffffffu, sum, off);
        ssq += __shfl_xor_sync(0xffffffffu, ssq, off);
    }
    int w = tid >> 5;
    if ((tid & 31) == 0) { r1[w] = sum; r2[w] = ssq; }
    __syncthreads();
    if (tid == 0) {
        float s = r1[0]+r1[1]+r1[2]+r1[3];
        float q = r2[0]+r2[1]+r2[2]+r2[3];
        float mean = s * (1.f/DIM);
        float var  = q * (1.f/DIM) - mean*mean;
        meanf[row] = mean;
        rstdf[row] = rsqrtf(var + 1e-5f);
    }
}

// ---------------- small GEMM (f32x2 mainloop, double buffered, optional inline LN-A) ----
#define GBM 16
#define GBN 64
#define GBK 32
#define GBM2 18
#define GBN2 68

struct GPtrs {
    const float* A; const float* B; const float* bias; const float* res; float* C;
    const float* lnm; const float* lnr; const float* lng; const float* lnb;
};

template<bool TRANSA, bool TRANSB, int ACT, bool RESID, bool LNA>
__global__ __launch_bounds__(128) void gemm16(
    GPtrs p0, GPtrs p1, int lda, int ldb, int ldc, int K)
{
    __shared__ __align__(16) u64   As2[2][GBK*GBM2];
    __shared__ __align__(16) float Bs [2][GBK*GBN2];

    GPtrs P = (blockIdx.z == 0) ? p0 : p1;
    const float* __restrict__ A = P.A;
    const float* __restrict__ B = P.B;

    int tid = threadIdx.x;
    int m0 = blockIdx.x * GBM;
    int n0 = blockIdx.y * GBN;
    int tx = tid & 15;
    int ty = tid >> 4;

    int a_m, a_k;
    if (TRANSA) { a_k = tid >> 2; a_m = (tid & 3) * 4; }
    else        { a_m = tid >> 3; a_k = (tid & 7) * 4; }

    float ln_m = 0.f, ln_r = 1.f;
    if (LNA) { ln_m = P.lnm[m0 + a_m]; ln_r = P.lnr[m0 + a_m]; }

    float4 ar;
    float4 br[4];

    u64 acc00 = 0ull, acc01 = 0ull, acc10 = 0ull, acc11 = 0ull;
    int nT = K / GBK;

    #define LOAD_A(t) do { \
        if (TRANSA) ar = *(const float4*)&A[(size_t)((t)*GBK + a_k)*lda + m0 + a_m]; \
        else        ar = *(const float4*)&A[(size_t)(m0 + a_m)*lda + (t)*GBK + a_k]; \
        if (LNA) { \
            float4 lg = *(const float4*)&P.lng[(t)*GBK + a_k]; \
            float4 lb = *(const float4*)&P.lnb[(t)*GBK + a_k]; \
            ar.x = (ar.x - ln_m)*ln_r*lg.x + lb.x; \
            ar.y = (ar.y - ln_m)*ln_r*lg.y + lb.y; \
            ar.z = (ar.z - ln_m)*ln_r*lg.z + lb.z; \
            ar.w = (ar.w - ln_m)*ln_r*lg.w + lb.w; \
        } \
    } while (0)
    #define LOAD_B(t) do { \
        _Pragma("unroll") \
        for (int it = 0; it < 4; it++) { \
            int idx = tid + it*128; \
            if (TRANSB) { int n = idx >> 3, kq = (idx & 7)*4; \
                br[it] = *(const float4*)&B[(size_t)(n0+n)*ldb + (t)*GBK + kq]; } \
            else { int kk = idx >> 4, nq = (idx & 15)*4; \
                br[it] = *(const float4*)&B[(size_t)((t)*GBK+kk)*ldb + n0 + nq]; } \
        } \
    } while (0)
    #define STORE_AB(buf) do { \
        if (TRANSA) { \
            u64* dst = &As2[buf][a_k*GBM2 + a_m]; \
            dst[0] = pk2(ar.x, ar.x); dst[1] = pk2(ar.y, ar.y); \
            dst[2] = pk2(ar.z, ar.z); dst[3] = pk2(ar.w, ar.w); \
        } else { \
            As2[buf][(a_k+0)*GBM2 + a_m] = pk2(ar.x, ar.x); \
            As2[buf][(a_k+1)*GBM2 + a_m] = pk2(ar.y, ar.y); \
            As2[buf][(a_k+2)*GBM2 + a_m] = pk2(ar.z, ar.z); \
            As2[buf][(a_k+3)*GBM2 + a_m] = pk2(ar.w, ar.w); \
        } \
        _Pragma("unroll") \
        for (int it = 0; it < 4; it++) { \
            int idx = tid + it*128; \
            if (TRANSB) { int n = idx >> 3, kq = (idx & 7)*4; \
                Bs[buf][(kq+0)*GBN2 + n] = br[it].x; \
                Bs[buf][(kq+1)*GBN2 + n] = br[it].y; \
                Bs[buf][(kq+2)*GBN2 + n] = br[it].z; \
                Bs[buf][(kq+3)*GBN2 + n] = br[it].w; \
            } else { int kk = idx >> 4, nq = (idx & 15)*4; \
                *(float4*)&Bs[buf][kk*GBN2 + nq] = br[it]; } \
        } \
    } while (0)

    LOAD_A(0); LOAD_B(0);
    STORE_AB(0);
    __syncthreads();

    for (int t = 0; t < nT; t++) {
        int cur = t & 1;
        bool more = (t+1 < nT);
        if (more) { LOAD_A(t+1); LOAD_B(t+1); }
#pragma unroll
        for (int kk = 0; kk < GBK; kk++) {
            ulonglong2 aa = *(const ulonglong2*)&As2[cur][kk*GBM2 + ty*2];
            ulonglong2 bb = *(const ulonglong2*)&Bs [cur][kk*GBN2 + tx*4];
            acc00 = fma2_(aa.x, bb.x, acc00);
            acc01 = fma2_(aa.x, bb.y, acc01);
            acc10 = fma2_(aa.y, bb.x, acc10);
            acc11 = fma2_(aa.y, bb.y, acc11);
        }
        if (more) {
            __syncthreads();
            STORE_AB((t+1) & 1);
            __syncthreads();
        }
    }
    #undef LOAD_A
    #undef LOAD_B
    #undef STORE_AB

    float c00a,c00b,c01a,c01b,c10a,c10b,c11a,c11b;
    upk2(acc00, c00a, c00b); upk2(acc01, c01a, c01b);
    upk2(acc10, c10a, c10b); upk2(acc11, c11a, c11b);

    float4 bv = make_float4(0.f,0.f,0.f,0.f);
    if (P.bias) bv = *(const float4*)&P.bias[n0 + tx*4];

    float4 o0 = make_float4(c00a+bv.x, c00b+bv.y, c01a+bv.z, c01b+bv.w);
    float4 o1 = make_float4(c10a+bv.x, c10b+bv.y, c11a+bv.z, c11b+bv.w);
    if (ACT == 1) {
        o0.x=fmaxf(o0.x,0.f); o0.y=fmaxf(o0.y,0.f); o0.z=fmaxf(o0.z,0.f); o0.w=fmaxf(o0.w,0.f);
        o1.x=fmaxf(o1.x,0.f); o1.y=fmaxf(o1.y,0.f); o1.z=fmaxf(o1.z,0.f); o1.w=fmaxf(o1.w,0.f);
    }
    size_t r0 = (size_t)(m0 + ty*2)*ldc + n0 + tx*4;
    size_t r1 = r0 + ldc;
    if (RESID) {
        float4 q0 = *(const float4*)&P.res[r0];
        float4 q1 = *(const float4*)&P.res[r1];
        o0.x+=q0.x; o0.y+=q0.y; o0.z+=q0.z; o0.w+=q0.w;
        o1.x+=q1.x; o1.y+=q1.y; o1.z+=q1.z; o1.w+=q1.w;
    }
    *(float4*)&P.C[r0] = o0;
    *(float4*)&P.C[r1] = o1;
}

// ---------------- fused attention pass, v2 ----------------
// 256 threads, grid (CH, BATCH). Group = 16 tokens, 2 per warp.
// Phase 1: warp w LNs tokens 2w,2w+1 (one qk smem read feeds both), softmax.
// Phase 2: warp w owns D-slice [64w,64w+64): all 8 slot accumulators in regs,
//          one LDS.64 per token + broadcast p pairs.
#define ATTN_SMEM (NSLOT*DIM*4 + GTOK*DIM*4 + 2*DIM*4 + GTOK*NSLOT*8 + NSLOT*4 + NSLOT*NSLOT*4 + 64)

__global__ __launch_bounds__(256, 2) void attn_kernel2(
    const float* __restrict__ X,
    const float* __restrict__ g_in, const float* __restrict__ be_in,
    const float* __restrict__ QK, const float* __restrict__ QB,
    float* __restrict__ Upart, float* __restrict__ Spart)
{
    extern __shared__ __align__(16) char smraw[];
    float* qks = (float*)smraw;                       // [8][512]
    float* xs  = qks + NSLOT*DIM;                     // [16][512]
    float* gbs = xs + GTOK*DIM;                       // [2][512]
    u64*   psd = (u64*)(gbs + 2*DIM);                 // [16][8] duplicated pairs
    float* qbs = (float*)(psd + GTOK*NSLOT);          // [8]
    float* sred= qbs + NSLOT;                         // [8][8]

    int b   = blockIdx.y;
    int ch  = blockIdx.x;
    int tid = threadIdx.x;
    int w = tid >> 5;
    int l = tid & 31;
    int cb4 = l * 4;

    for (int i = tid*4; i < NSLOT*DIM; i += 1024)
        *(float4*)&qks[i] = *(const float4*)&QK[(size_t)b*NSLOT*DIM + i];
    if (tid < 128) {
        *(float4*)&gbs[tid*4]       = *(const float4*)&g_in[tid*4];
        *(float4*)&gbs[DIM + tid*4] = *(const float4*)&be_in[tid*4];
    }
    if (tid < NSLOT) qbs[tid] = QB[b*NSLOT + tid];
    __syncthreads();

    u64 U2[8];
#pragma unroll
    for (int i = 0; i < 8; i++) U2[i] = 0ull;
    float sl = 0.f;

    const float scale = 0.04419417382415922f;   // 512^-0.5
    int j0 = ch * CTOK;
    int tA = 2*w, tB = 2*w + 1;
    int xoff = w*64 + l*2;

    for (int g = 0; g < CTOK/GTOK; g++) {
        // ======== phase 1: LN + dots for tokens tA,tB of this group ========
        const float* xrA = X + ((size_t)b*NTOK + j0 + g*GTOK + tA)*DIM;
        const float* xrB = xrA + DIM;
        u64 xvA[8], xvB[8];
        u64 sA2 = 0ull, qA2 = 0ull, sB2 = 0ull, qB2 = 0ull;
#pragma unroll
        for (int s = 0; s < 4; s++) {
            ulonglong2 a2 = *(const ulonglong2*)&xrA[s*128 + cb4];
            ulonglong2 b2 = *(const ulonglong2*)&xrB[s*128 + cb4];
            xvA[2*s] = a2.x; xvA[2*s+1] = a2.y;
            xvB[2*s] = b2.x; xvB[2*s+1] = b2.y;
            sA2 = add2_(sA2, a2.x); sA2 = add2_(sA2, a2.y);
            qA2 = fma2_(a2.x, a2.x, qA2); qA2 = fma2_(a2.y, a2.y, qA2);
            sB2 = add2_(sB2, b2.x); sB2 = add2_(sB2, b2.y);
            qB2 = fma2_(b2.x, b2.x, qB2); qB2 = fma2_(b2.y, b2.y, qB2);
        }
        float t0, t1;
        upk2(sA2, t0, t1); float sumA = t0 + t1;
        upk2(qA2, t0, t1); float ssqA = t0 + t1;
        upk2(sB2, t0, t1); float sumB = t0 + t1;
        upk2(qB2, t0, t1); float ssqB = t0 + t1;
#pragma unroll
        for (int off = 16; off > 0; off >>= 1) {
            sumA += __shfl_xor_sync(0xffffffffu, sumA, off);
            ssqA += __shfl_xor_sync(0xffffffffu, ssqA, off);
            sumB += __shfl_xor_sync(0xffffffffu, sumB, off);
            ssqB += __shfl_xor_sync(0xffffffffu, ssqB, off);
        }
        float meanA = sumA * (1.f/DIM);
        float invA  = rsqrtf(ssqA*(1.f/DIM) - meanA*meanA + 1e-5f);
        float meanB = sumB * (1.f/DIM);
        float invB  = rsqrtf(ssqB*(1.f/DIM) - meanB*meanB + 1e-5f);
        u64 invA2 = pk2(invA, invA), nmA2 = pk2(-meanA, -meanA);
        u64 invB2 = pk2(invB, invB), nmB2 = pk2(-meanB, -meanB);

        u64 dA2[8], dB2[8];
#pragma unroll
        for (int i = 0; i < 8; i++) { dA2[i] = 0ull; dB2[i] = 0ull; }
#pragma unroll
        for (int s = 0; s < 4; s++) {
            int c = s*128 + cb4;
            ulonglong2 g2 = *(const ulonglong2*)&gbs[c];
            ulonglong2 b2 = *(const ulonglong2*)&gbs[DIM + c];
            u64 giA0 = mul2_(g2.x, invA2), giA1 = mul2_(g2.y, invA2);
            u64 kA0  = fma2_(nmA2, giA0, b2.x), kA1 = fma2_(nmA2, giA1, b2.y);
            u64 xnA0 = fma2_(xvA[2*s],   giA0, kA0);
            u64 xnA1 = fma2_(xvA[2*s+1], giA1, kA1);
            *(ulonglong2*)&xs[tA*DIM + c] = make_ulonglong2(xnA0, xnA1);
            u64 giB0 = mul2_(g2.x, invB2), giB1 = mul2_(g2.y, invB2);
            u64 kB0  = fma2_(nmB2, giB0, b2.x), kB1 = fma2_(nmB2, giB1, b2.y);
            u64 xnB0 = fma2_(xvB[2*s],   giB0, kB0);
            u64 xnB1 = fma2_(xvB[2*s+1], giB1, kB1);
            *(ulonglong2*)&xs[tB*DIM + c] = make_ulonglong2(xnB0, xnB1);
#pragma unroll
            for (int i = 0; i < 8; i++) {
                ulonglong2 q2 = *(const ulonglong2*)&qks[i*DIM + c];
                dA2[i] = fma2_(q2.x, xnA0, dA2[i]);
                dA2[i] = fma2_(q2.y, xnA1, dA2[i]);
                dB2[i] = fma2_(q2.x, xnB0, dB2[i]);
                dB2[i] = fma2_(q2.y, xnB1, dB2[i]);
            }
        }
        float dA[8], dB[8];
#pragma unroll
        for (int i = 0; i < 8; i++) {
            float a0, a1;
            upk2(dA2[i], a0, a1); dA[i] = a0 + a1;
            upk2(dB2[i], a0, a1); dB[i] = a0 + a1;
        }
#pragma unroll
        for (int off = 16; off > 0; off >>= 1) {
#pragma unroll
            for (int i = 0; i < 8; i++) {
                dA[i] += __shfl_xor_sync(0xffffffffu, dA[i], off);
                dB[i] += __shfl_xor_sync(0xffffffffu, dB[i], off);
            }
        }
        // softmax over slots (redundant per lane)
        float mxA = -1e30f, mxB = -1e30f;
#pragma unroll
        for (int i = 0; i < 8; i++) {
            dA[i] = (dA[i] + qbs[i]) * scale; mxA = fmaxf(mxA, dA[i]);
            dB[i] = (dB[i] + qbs[i]) * scale; mxB = fmaxf(mxB, dB[i]);
        }
        float seA = 0.f, seB = 0.f;
#pragma unroll
        for (int i = 0; i < 8; i++) {
            dA[i] = __expf(dA[i] - mxA); seA += dA[i];
            dB[i] = __expf(dB[i] - mxB); seB += dB[i];
        }
        float rA = 1.f/seA, rB = 1.f/seB;
        float pa = 0.f, pb = 0.f;
        int ls = l & 7;
#pragma unroll
        for (int i = 0; i < 8; i++) {
            if (ls == i) { pa = dA[i]*rA + 1e-8f; pb = dB[i]*rB + 1e-8f; }
        }
        sl += pa + pb;
        if (l < 8)       psd[tA*NSLOT + l]      = pk2(pa, pa);
        else if (l < 16) psd[tB*NSLOT + (l-8)]  = pk2(pb, pb);
        __syncthreads();

        // ======== phase 2: warp w accumulates its 64-dim slice for all slots ========
#pragma unroll
        for (int t = 0; t < GTOK; t++) {
            u64 x2 = *(const u64*)&xs[t*DIM + xoff];
            ulonglong2 p01 = *(const ulonglong2*)&psd[t*NSLOT + 0];
            ulonglong2 p23 = *(const ulonglong2*)&psd[t*NSLOT + 2];
            ulonglong2 p45 = *(const ulonglong2*)&psd[t*NSLOT + 4];
            ulonglong2 p67 = *(const ulonglong2*)&psd[t*NSLOT + 6];
            U2[0] = fma2_(p01.x, x2, U2[0]); U2[1] = fma2_(p01.y, x2, U2[1]);
            U2[2] = fma2_(p23.x, x2, U2[2]); U2[3] = fma2_(p23.y, x2, U2[3]);
            U2[4] = fma2_(p45.x, x2, U2[4]); U2[5] = fma2_(p45.y, x2, U2[5]);
            U2[6] = fma2_(p67.x, x2, U2[6]); U2[7] = fma2_(p67.y, x2, U2[7]);
        }
        __syncthreads();
    }

    size_t ub = ((size_t)(b*CH + ch)*NSLOT)*DIM + xoff;
#pragma unroll
    for (int i = 0; i < 8; i++)
        *(u64*)&Upart[ub + (size_t)i*DIM] = U2[i];
    if (l < 8) sred[w*8 + l] = sl;
    __syncthreads();
    if (tid < 8) {
        float s = 0.f;
#pragma unroll
        for (int w2 = 0; w2 < 8; w2++) s += sred[w2*8 + tid];
        Spart[(b*CH + ch)*NSLOT + tid] = s;
    }
}

// ---------------- reduce partials ----------------
__global__ void finish_kernel(const float* __restrict__ Upart,
                              const float* __restrict__ Spart,
                              float* __restrict__ Upre)
{
    int bi = blockIdx.x;            // b*8 + i
    int b = bi >> 3, i = bi & 7;
    int tid = threadIdx.x;          // 128
    __shared__ float ssum_s;
    if (tid < 32) {
        float s = Spart[(b*CH + tid)*NSLOT + i];
#pragma unroll
        for (int off = 16; off > 0; off >>= 1) s += __shfl_xor_sync(0xffffffffu, s, off);
        if (tid == 0) ssum_s = s;
    }
    __syncthreads();
    float rs = 1.f / ssum_s;
    int c = tid * 4;
    float4 acc = make_float4(0.f,0.f,0.f,0.f);
    for (int chn = 0; chn < CH; chn++) {
        float4 v = *(const float4*)&Upart[(((size_t)b*CH + chn)*NSLOT + i)*DIM + c];
        acc.x += v.x; acc.y += v.y; acc.z += v.z; acc.w += v.w;
    }
    acc.x*=rs; acc.y*=rs; acc.z*=rs; acc.w*=rs;
    *(float4*)&Upre[(size_t)bi*DIM + c] = acc;
}

// ---------------- host orchestration ----------------
extern "C" void kernel_launch(void* const* d_in, const int* in_sizes, int n_in,
                              void* d_out, int out_size)
{
    const float* inputs = (const float*)d_in[0];
    const float* noise  = (const float*)d_in[1];
    const float* mu     = (const float*)d_in[2];
    const float* sg     = (const float*)d_in[3];
    const float* Wq = (const float*)d_in[4];
    const float* bq = (const float*)d_in[5];
    const float* Wk = (const float*)d_in[6];
    const float* bk = (const float*)d_in[7];
    const float* Wv = (const float*)d_in[8];
    const float* bv = (const float*)d_in[9];
    const float* W_ih = (const float*)d_in[10];
    const float* b_ih = (const float*)d_in[11];
    const float* W_hh = (const float*)d_in[12];
    const float* b_hh = (const float*)d_in[13];
    const float* W1 = (const float*)d_in[14];
    const float* b1 = (const float*)d_in[15];
    const float* W2 = (const float*)d_in[16];
    const float* b2 = (const float*)d_in[17];
    const float* gin  = (const float*)d_in[18];
    const float* bein = (const float*)d_in[19];
    const float* gsl  = (const float*)d_in[20];
    const float* besl = (const float*)d_in[21];
    const float* gff  = (const float*)d_in[22];
    const float* beff = (const float*)d_in[23];

    float* slots = (float*)d_out;

    void* p;
    cudaGetSymbolAddress(&p, g_qk);    float* qk    = (float*)p;
    cudaGetSymbolAddress(&p, g_qb);    float* qb    = (float*)p;
    cudaGetSymbolAddress(&p, g_Mqk);   float* Mqk   = (float*)p;
    cudaGetSymbolAddress(&p, g_rqk);   float* rqk   = (float*)p;
    cudaGetSymbolAddress(&p, g_u);     float* uvec  = (float*)p;
    cudaGetSymbolAddress(&p, g_c0);    float* c0    = (float*)p;
    cudaGetSymbolAddress(&p, g_gu);    float* gu    = (float*)p;
    cudaGetSymbolAddress(&p, g_sc);    float* sc    = (float*)p;
    cudaGetSymbolAddress(&p, g_mq);    float* mq    = (float*)p;
    cudaGetSymbolAddress(&p, g_rq);    float* rq    = (float*)p;
    cudaGetSymbolAddress(&p, g_mf);    float* mf    = (float*)p;
    cudaGetSymbolAddress(&p, g_rf);    float* rf    = (float*)p;
    cudaGetSymbolAddress(&p, g_upart); float* upart = (float*)p;
    cudaGetSymbolAddress(&p, g_spart); float* spart = (float*)p;
    cudaGetSymbolAddress(&p, g_upre);  float* upre  = (float*)p;
    cudaGetSymbolAddress(&p, g_upd);   float* upd   = (float*)p;
    cudaGetSymbolAddress(&p, g_gx);    float* gx    = (float*)p;
    cudaGetSymbolAddress(&p, g_gh);    float* gh    = (float*)p;
    cudaGetSymbolAddress(&p, g_h1);    float* h1    = (float*)p;

    static bool attr_done = false;
    if (!attr_done) {
        cudaFuncSetAttribute(attn_kernel2, cudaFuncAttributeMaxDynamicSharedMemorySize, ATTN_SMEM);
        attr_done = true;
    }

    GPtrs Z{};  // zero template

    init_slots_kernel<<<(ROWS*DIM + 255)/256, 256>>>(noise, mu, sg, slots);
    precompute_vecs<<<9, 128>>>(Wq, Wk, bq, bk, rqk, uvec, c0);
    precompute2<<<1, 512>>>(gsl, besl, uvec, c0, gu, sc);

    // Mqk = Wq^T @ Wk
    {
        GPtrs a = Z; a.A = Wq; a.B = Wk; a.C = Mqk;
        gemm16<true,false,0,false,false><<<dim3(DIM/GBM, DIM/GBN, 1), 128>>>(a, a, DIM, DIM, DIM, DIM);
    }

    for (int it = 0; it < 3; it++) {
        // per-row LN stats for q-path + fused qb
        stats_q_kernel<<<ROWS/8, 256>>>(slots, gu, sc, mq, rq, qb);
        // qk = LN(slots) @ Mqk + rqk  (LN inline on A staging)
        {
            GPtrs a = Z; a.A = slots; a.B = Mqk; a.bias = rqk; a.C = qk;
            a.lnm = mq; a.lnr = rq; a.lng = gsl; a.lnb = besl;
            gemm16<false,false,0,false,true><<<dim3(ROWS/GBM, DIM/GBN, 1), 128>>>(a, a, DIM, DIM, DIM, DIM);
        }
        // fused attention streaming pass
        attn_kernel2<<<dim3(CH, BATCH), 256, ATTN_SMEM>>>(inputs, gin, bein, qk, qb, upart, spart);
        finish_kernel<<<ROWS, 128>>>(upart, spart, upre);
        // updates = Upre @ Wv^T + bv
        {
            GPtrs a = Z; a.A = upre; a.B = Wv; a.bias = bv; a.C = upd;
            gemm16<false,true,0,false,false><<<dim3(ROWS/GBM, DIM/GBN, 1), 128>>>(a, a, DIM, DIM, DIM, DIM);
        }
        // GRU gates (batched pair)
        {
            GPtrs a = Z; a.A = upd;   a.B = W_ih; a.bias = b_ih; a.C = gx;
            GPtrs b = Z; b.A = slots; b.B = W_hh; b.bias = b_hh; b.C = gh;
            gemm16<false,true,0,false,false><<<dim3(ROWS/GBM, (3*DIM)/GBN, 2), 128>>>(a, b, DIM, DIM, 3*DIM, DIM);
        }
        // GRU elementwise + ff-LN stats
        gru_ln_kernel<<<ROWS, 128>>>(gx, gh, slots, mf, rf);
        // h1 = relu(LN_ff(slots) @ W1^T + b1)   (LN inline on A staging)
        {
            GPtrs a = Z; a.A = slots; a.B = W1; a.bias = b1; a.C = h1;
            a.lnm = mf; a.lnr = rf; a.lng = gff; a.lnb = beff;
            gemm16<false,true,1,false,true><<<dim3(ROWS/GBM, DIM/GBN, 1), 128>>>(a, a, DIM, DIM, DIM, DIM);
        }
        // slots += h1 @ W2^T + b2
        {
            GPtrs a = Z; a.A = h1; a.B = W2; a.bias = b2; a.res = slots; a.C = slots;
            gemm16<false,true,0,true,false><<<dim3(ROWS/GBM, DIM/GBN, 1), 128>>>(a, a, DIM, DIM, DIM, DIM);
        }
    }
}

// round 13
// speedup vs baseline: 1.4873x; 1.0812x over previous
#include <cuda_runtime.h>
#include <math.h>

#define BATCH 32
#define NTOK  4096
#define NSLOT 8
#define DIM   512
#define CH    32
#define CTOK  128
#define GTOK  16
#define ROWS  256

typedef unsigned long long u64;

// ---------------- packed f32x2 helpers ----------------
__device__ __forceinline__ u64 pk2(float lo, float hi) {
    u64 r; asm("mov.b64 %0, {%1, %2};" : "=l"(r) : "f"(lo), "f"(hi)); return r;
}
__device__ __forceinline__ void upk2(u64 v, float& a, float& b) {
    asm("mov.b64 {%0, %1}, %2;" : "=f"(a), "=f"(b) : "l"(v));
}
__device__ __forceinline__ u64 fma2_(u64 a, u64 b, u64 c) {
    u64 d; asm("fma.rn.f32x2 %0, %1, %2, %3;" : "=l"(d) : "l"(a), "l"(b), "l"(c)); return d;
}
__device__ __forceinline__ u64 add2_(u64 a, u64 b) {
    u64 d; asm("add.rn.f32x2 %0, %1, %2;" : "=l"(d) : "l"(a), "l"(b)); return d;
}
__device__ __forceinline__ u64 mul2_(u64 a, u64 b) {
    u64 d; asm("mul.rn.f32x2 %0, %1, %2;" : "=l"(d) : "l"(a), "l"(b)); return d;
}

// ---------------- device scratch (split-K partial planes where noted) ----------------
__device__ float g_qk   [2*ROWS*DIM];
__device__ float g_qb   [ROWS];
__device__ float g_Mqk  [DIM*DIM];
__device__ float g_rqk  [DIM];
__device__ float g_u    [DIM];
__device__ float g_c0   [1];
__device__ float g_scp  [8];          // 4 blocks x (s1, s2) partials
__device__ float g_mq   [ROWS];
__device__ float g_rq   [ROWS];
__device__ float g_mf   [ROWS];
__device__ float g_rf   [ROWS];
__device__ float g_upart[BATCH*CH*NSLOT*DIM];
__device__ float g_spart[BATCH*CH*NSLOT];
__device__ float g_upre [ROWS*DIM];
__device__ float g_upd  [2*ROWS*DIM];
__device__ float g_gx   [2*ROWS*3*DIM];
__device__ float g_gh   [2*ROWS*3*DIM];
__device__ float g_h1   [2*ROWS*DIM];

// ---------------- slot init ----------------
__global__ void init_slots_kernel(const float* __restrict__ noise,
                                  const float* __restrict__ mu,
                                  const float* __restrict__ sg,
                                  float* __restrict__ slots)
{
    int idx = blockIdx.x * blockDim.x + threadIdx.x;
    if (idx >= ROWS*DIM) return;
    int c = idx & (DIM-1);
    slots[idx] = mu[c] + fabsf(sg[c]) * noise[idx];
}

// ---------------- merged one-time prologue (grid 9, 128 thr) ----------------
// bid 0-3: rqk[f] = sum_d bq[d]*Wk[d,f]
// bid 4-7: uvec[e] = sum_d bk[d]*Wq[d,e]; partial sums s1 = gsl*u, s2 = besl*u
// bid 8:   c0 = bq.bk
__global__ void prologue_kernel(const float* __restrict__ Wq, const float* __restrict__ Wk,
                                const float* __restrict__ bq, const float* __restrict__ bk,
                                const float* __restrict__ gsl, const float* __restrict__ besl,
                                float* __restrict__ rqk, float* __restrict__ uvec,
                                float* __restrict__ scp, float* __restrict__ c0)
{
    int bid = blockIdx.x;
    int tid = threadIdx.x;
    if (bid < 4) {
        int f = bid*128 + tid;
        float acc = 0.f;
#pragma unroll 8
        for (int d = 0; d < DIM; d++) acc += __ldg(&bq[d]) * Wk[(size_t)d*DIM + f];
        rqk[f] = acc;
    } else if (bid < 8) {
        __shared__ float r1[128], r2[128];
        int e = (bid-4)*128 + tid;
        float acc = 0.f;
#pragma unroll 8
        for (int d = 0; d < DIM; d++) acc += __ldg(&bk[d]) * Wq[(size_t)d*DIM + e];
        uvec[e] = acc;
        r1[tid] = gsl[e]*acc;
        r2[tid] = besl[e]*acc;
        __syncthreads();
        for (int s = 64; s > 0; s >>= 1) {
            if (tid < s) { r1[tid] += r1[tid+s]; r2[tid] += r2[tid+s]; }
            __syncthreads();
        }
        if (tid == 0) { scp[2*(bid-4)+0] = r1[0]; scp[2*(bid-4)+1] = r2[0]; }
    } else {
        __shared__ float red[128];
        float acc = 0.f;
        for (int d = tid; d < DIM; d += 128) acc += bq[d]*bk[d];
        red[tid] = acc; __syncthreads();
        for (int s = 64; s > 0; s >>= 1) { if (tid < s) red[tid] += red[tid+s]; __syncthreads(); }
        if (tid == 0) *c0 = red[0];
    }
}

// ---------------- per-row LN stats for q-path (+ fused qb) ----------------
__global__ void stats_q_kernel(const float* __restrict__ slots,
                               const float* __restrict__ gsl,
                               const float* __restrict__ uvec,
                               const float* __restrict__ scp,
                               const float* __restrict__ c0,
                               float* __restrict__ meanq, float* __restrict__ rstdq,
                               float* __restrict__ qb)
{
    int row = blockIdx.x * 8 + (threadIdx.x >> 5);
    int l   = threadIdx.x & 31;
    const float* x = slots + (size_t)row * DIM;
    float sum = 0.f, ssq = 0.f, dgu = 0.f;
#pragma unroll
    for (int s = 0; s < 4; s++) {
        int c = s*128 + l*4;
        float4 v  = *(const float4*)&x[c];
        float4 gv = *(const float4*)&gsl[c];
        float4 uv = *(const float4*)&uvec[c];
        sum += v.x + v.y + v.z + v.w;
        ssq += v.x*v.x + v.y*v.y + v.z*v.z + v.w*v.w;
        dgu += v.x*gv.x*uv.x + v.y*gv.y*uv.y + v.z*gv.z*uv.z + v.w*gv.w*uv.w;
    }
#pragma unroll
    for (int off = 16; off > 0; off >>= 1) {
        sum += __shfl_xor_sync(0xffffffffu, sum, off);
        ssq += __shfl_xor_sync(0xffffffffu, ssq, off);
        dgu += __shfl_xor_sync(0xffffffffu, dgu, off);
    }
    if (l == 0) {
        float S1 = scp[0] + scp[2] + scp[4] + scp[6];
        float S2 = scp[1] + scp[3] + scp[5] + scp[7] + *c0;
        float mean = sum * (1.f/DIM);
        float var  = ssq * (1.f/DIM) - mean*mean;
        float r    = rsqrtf(var + 1e-5f);
        meanq[row] = mean;
        rstdq[row] = r;
        qb[row]    = r*(dgu - mean*S1) + S2;
    }
}

// ---------------- GRU elementwise (sums split-K gate partials) + ff-LN stats ----------------
__global__ void gru_ln_kernel(const float* __restrict__ gx, const float* __restrict__ gh,
                              float* __restrict__ slots,
                              float* __restrict__ meanf, float* __restrict__ rstdf)
{
    __shared__ float r1[4], r2[4];
    int row = blockIdx.x;
    int tid = threadIdx.x;      // 128
    int c = tid * 4;
    const float* gxm = gx + (size_t)row*3*DIM;
    const float* ghm = gh + (size_t)row*3*DIM;
    const size_t PO = (size_t)ROWS*3*DIM;
    float4 xr = *(const float4*)&gxm[c];
    float4 xz = *(const float4*)&gxm[DIM + c];
    float4 xn = *(const float4*)&gxm[2*DIM + c];
    float4 hr = *(const float4*)&ghm[c];
    float4 hz = *(const float4*)&ghm[DIM + c];
    float4 hn = *(const float4*)&ghm[2*DIM + c];
    float4 xr2 = *(const float4*)&gxm[PO + c];
    float4 xz2 = *(const float4*)&gxm[PO + DIM + c];
    float4 xn2 = *(const float4*)&gxm[PO + 2*DIM + c];
    float4 hr2 = *(const float4*)&ghm[PO + c];
    float4 hz2 = *(const float4*)&ghm[PO + DIM + c];
    float4 hn2 = *(const float4*)&ghm[PO + 2*DIM + c];
    xr.x+=xr2.x; xr.y+=xr2.y; xr.z+=xr2.z; xr.w+=xr2.w;
    xz.x+=xz2.x; xz.y+=xz2.y; xz.z+=xz2.z; xz.w+=xz2.w;
    xn.x+=xn2.x; xn.y+=xn2.y; xn.z+=xn2.z; xn.w+=xn2.w;
    hr.x+=hr2.x; hr.y+=hr2.y; hr.z+=hr2.z; hr.w+=hr2.w;
    hz.x+=hz2.x; hz.y+=hz2.y; hz.z+=hz2.z; hz.w+=hz2.w;
    hn.x+=hn2.x; hn.y+=hn2.y; hn.z+=hn2.z; hn.w+=hn2.w;
    float4 h4 = *(const float4*)&slots[(size_t)row*DIM + c];
    float4 o;
    {
        float r = 1.f/(1.f + __expf(-(xr.x + hr.x)));
        float z = 1.f/(1.f + __expf(-(xz.x + hz.x)));
        float n = tanhf(xn.x + r*hn.x);
        o.x = (1.f - z)*n + z*h4.x;
    }
    {
        float r = 1.f/(1.f + __expf(-(xr.y + hr.y)));
        float z = 1.f/(1.f + __expf(-(xz.y + hz.y)));
        float n = tanhf(xn.y + r*hn.y);
        o.y = (1.f - z)*n + z*h4.y;
    }
    {
        float r = 1.f/(1.f + __expf(-(xr.z + hr.z)));
        float z = 1.f/(1.f + __expf(-(xz.z + hz.z)));
        float n = tanhf(xn.z + r*hn.z);
        o.z = (1.f - z)*n + z*h4.z;
    }
    {
        float r = 1.f/(1.f + __expf(-(xr.w + hr.w)));
        float z = 1.f/(1.f + __expf(-(xz.w + hz.w)));
        float n = tanhf(xn.w + r*hn.w);
        o.w = (1.f - z)*n + z*h4.w;
    }
    *(float4*)&slots[(size_t)row*DIM + c] = o;
    float sum = o.x + o.y + o.z + o.w;
    float ssq = o.x*o.x + o.y*o.y + o.z*o.z + o.w*o.w;
#pragma unroll
    for (int off = 16; off > 0; off >>= 1) {
        sum += __shfl_xor_sync(0xffffffffu, sum, off);
        ssq += __shfl_xor_sync(0xffffffffu, ssq, off);
    }
    int w = tid >> 5;
    if ((tid & 31) == 0) { r1[w] = sum; r2[w] = ssq; }
    __syncthreads();
    if (tid == 0) {
        float s = r1[0]+r1[1]+r1[2]+r1[3];
        float q = r2[0]+r2[1]+r2[2]+r2[3];
        float mean = s * (1.f/DIM);
        float var  = q * (1.f/DIM) - mean*mean;
        meanf[row] = mean;
        rstdf[row] = rsqrtf(var + 1e-5f);
    }
}

// ---------------- small GEMM: split-K, f32x2 mainloop, register prefetch ----------------
#define GBM 16
#define GBN 64
#define GBK 32
#define GBM2 18
#define GBN2 68

struct GPtrs {
    const float* A; const float* A2; const float* B; const float* bias; const float* res;
    float* C; int cstride;
    const float* lnm; const float* lnr; const float* lng; const float* lnb;
};

template<bool TRANSA, bool TRANSB, bool RESID, bool LNA, int KS, bool RELUA>
__global__ __launch_bounds__(128) void gemm16(
    GPtrs p0, GPtrs p1, int lda, int ldb, int ldc, int K)
{
    __shared__ __align__(16) u64   As2[2][GBK*GBM2];
    __shared__ __align__(16) float Bs [2][GBK*GBN2];

    int khalf = (KS == 2) ? (blockIdx.z & 1) : 0;
    int pair  = (KS == 2) ? (blockIdx.z >> 1) : blockIdx.z;
    GPtrs P = (pair == 0) ? p0 : p1;
    int Keff = K / KS;

    const float* __restrict__ A  = P.A;
    const float* __restrict__ A2 = P.A2;
    const float* __restrict__ B  = P.B;
    const float* __restrict__ lng = P.lng;
    const float* __restrict__ lnb = P.lnb;
    if (KS == 2) {
        if (TRANSA) A += (size_t)khalf * Keff * lda;
        else        A += khalf * Keff;
        if (A2) A2 += khalf * Keff;
        if (TRANSB) B += khalf * Keff;
        else        B += (size_t)khalf * Keff * ldb;
        if (LNA) { lng += khalf * Keff; lnb += khalf * Keff; }
    }
    float* C = P.C + (size_t)khalf * P.cstride;

    int tid = threadIdx.x;
    int m0 = blockIdx.x * GBM;
    int n0 = blockIdx.y * GBN;
    int tx = tid & 15;
    int ty = tid >> 4;

    int a_m, a_k;
    if (TRANSA) { a_k = tid >> 2; a_m = (tid & 3) * 4; }
    else        { a_m = tid >> 3; a_k = (tid & 7) * 4; }

    float ln_m = 0.f, ln_r = 1.f;
    if (LNA) { ln_m = P.lnm[m0 + a_m]; ln_r = P.lnr[m0 + a_m]; }

    float4 ar;
    float4 br[4];

    u64 acc00 = 0ull, acc01 = 0ull, acc10 = 0ull, acc11 = 0ull;
    int nT = Keff / GBK;

    #define LOAD_A(t) do { \
        if (TRANSA) ar = *(const float4*)&A[(size_t)((t)*GBK + a_k)*lda + m0 + a_m]; \
        else        ar = *(const float4*)&A[(size_t)(m0 + a_m)*lda + (t)*GBK + a_k]; \
        if (!TRANSA && A2) { \
            float4 a2 = *(const float4*)&A2[(size_t)(m0 + a_m)*lda + (t)*GBK + a_k]; \
            ar.x += a2.x; ar.y += a2.y; ar.z += a2.z; ar.w += a2.w; \
        } \
        if (RELUA) { \
            ar.x = fmaxf(ar.x, 0.f); ar.y = fmaxf(ar.y, 0.f); \
            ar.z = fmaxf(ar.z, 0.f); ar.w = fmaxf(ar.w, 0.f); \
        } \
        if (LNA) { \
            float4 lg = *(const float4*)&lng[(t)*GBK + a_k]; \
            float4 lb = *(const float4*)&lnb[(t)*GBK + a_k]; \
            ar.x = (ar.x - ln_m)*ln_r*lg.x + lb.x; \
            ar.y = (ar.y - ln_m)*ln_r*lg.y + lb.y; \
            ar.z = (ar.z - ln_m)*ln_r*lg.z + lb.z; \
            ar.w = (ar.w - ln_m)*ln_r*lg.w + lb.w; \
        } \
    } while (0)
    #define LOAD_B(t) do { \
        _Pragma("unroll") \
        for (int it = 0; it < 4; it++) { \
            int idx = tid + it*128; \
            if (TRANSB) { int n = idx >> 3, kq = (idx & 7)*4; \
                br[it] = *(const float4*)&B[(size_t)(n0+n)*ldb + (t)*GBK + kq]; } \
            else { int kk = idx >> 4, nq = (idx & 15)*4; \
                br[it] = *(const float4*)&B[(size_t)((t)*GBK+kk)*ldb + n0 + nq]; } \
        } \
    } while (0)
    #define STORE_AB(buf) do { \
        if (TRANSA) { \
            u64* dst = &As2[buf][a_k*GBM2 + a_m]; \
            dst[0] = pk2(ar.x, ar.x); dst[1] = pk2(ar.y, ar.y); \
            dst[2] = pk2(ar.z, ar.z); dst[3] = pk2(ar.w, ar.w); \
        } else { \
            As2[buf][(a_k+0)*GBM2 + a_m] = pk2(ar.x, ar.x); \
            As2[buf][(a_k+1)*GBM2 + a_m] = pk2(ar.y, ar.y); \
            As2[buf][(a_k+2)*GBM2 + a_m] = pk2(ar.z, ar.z); \
            As2[buf][(a_k+3)*GBM2 + a_m] = pk2(ar.w, ar.w); \
        } \
        _Pragma("unroll") \
        for (int it = 0; it < 4; it++) { \
            int idx = tid + it*128; \
            if (TRANSB) { int n = idx >> 3, kq = (idx & 7)*4; \
                Bs[buf][(kq+0)*GBN2 + n] = br[it].x; \
                Bs[buf][(kq+1)*GBN2 + n] = br[it].y; \
                Bs[buf][(kq+2)*GBN2 + n] = br[it].z; \
                Bs[buf][(kq+3)*GBN2 + n] = br[it].w; \
            } else { int kk = idx >> 4, nq = (idx & 15)*4; \
                *(float4*)&Bs[buf][kk*GBN2 + nq] = br[it]; } \
        } \
    } while (0)

    LOAD_A(0); LOAD_B(0);
    STORE_AB(0);
    __syncthreads();

    for (int t = 0; t < nT; t++) {
        int cur = t & 1;
        bool more = (t+1 < nT);
        if (more) { LOAD_A(t+1); LOAD_B(t+1); }
        ulonglong2 aa = *(const ulonglong2*)&As2[cur][0*GBM2 + ty*2];
        ulonglong2 bb = *(const ulonglong2*)&Bs [cur][0*GBN2 + tx*4];
#pragma unroll
        for (int kk = 0; kk < GBK; kk++) {
            ulonglong2 aan, bbn;
            if (kk + 1 < GBK) {
                aan = *(const ulonglong2*)&As2[cur][(kk+1)*GBM2 + ty*2];
                bbn = *(const ulonglong2*)&Bs [cur][(kk+1)*GBN2 + tx*4];
            }
            acc00 = fma2_(aa.x, bb.x, acc00);
            acc01 = fma2_(aa.x, bb.y, acc01);
            acc10 = fma2_(aa.y, bb.x, acc10);
            acc11 = fma2_(aa.y, bb.y, acc11);
            if (kk + 1 < GBK) { aa = aan; bb = bbn; }
        }
        if (more) {
            __syncthreads();
            STORE_AB((t+1) & 1);
            __syncthreads();
        }
    }
    #undef LOAD_A
    #undef LOAD_B
    #undef STORE_AB

    float c00a,c00b,c01a,c01b,c10a,c10b,c11a,c11b;
    upk2(acc00, c00a, c00b); upk2(acc01, c01a, c01b);
    upk2(acc10, c10a, c10b); upk2(acc11, c11a, c11b);

    float4 bv = make_float4(0.f,0.f,0.f,0.f);
    if (P.bias && khalf == 0) bv = *(const float4*)&P.bias[n0 + tx*4];

    float4 o0 = make_float4(c00a+bv.x, c00b+bv.y, c01a+bv.z, c01b+bv.w);
    float4 o1 = make_float4(c10a+bv.x, c10b+bv.y, c11a+bv.z, c11b+bv.w);
    size_t r0 = (size_t)(m0 + ty*2)*ldc + n0 + tx*4;
    size_t r1 = r0 + ldc;
    if (RESID && khalf == 0) {
        float4 q0 = *(const float4*)&P.res[r0];
        float4 q1 = *(const float4*)&P.res[r1];
        o0.x+=q0.x; o0.y+=q0.y; o0.z+=q0.z; o0.w+=q0.w;
        o1.x+=q1.x; o1.y+=q1.y; o1.z+=q1.z; o1.w+=q1.w;
    }
    *(float4*)&C[r0] = o0;
    *(float4*)&C[r1] = o1;
}

// ---------------- fused attention pass ----------------
#define ATTN_SMEM (NSLOT*DIM*4 + GTOK*DIM*4 + 2*DIM*4 + GTOK*NSLOT*8 + NSLOT*4 + NSLOT*NSLOT*4 + 64)

__global__ __launch_bounds__(256, 3) void attn_kernel2(
    const float* __restrict__ X,
    const float* __restrict__ g_in, const float* __restrict__ be_in,
    const float* __restrict__ QK, const float* __restrict__ QB,
    float* __restrict__ Upart, float* __restrict__ Spart)
{
    extern __shared__ __align__(16) char smraw[];
    float* qks = (float*)smraw;                       // [8][512]
    float* xs  = qks + NSLOT*DIM;                     // [16][512]
    float* gbs = xs + GTOK*DIM;                       // [2][512]
    u64*   psd = (u64*)(gbs + 2*DIM);                 // [16][8]
    float* qbs = (float*)(psd + GTOK*NSLOT);          // [8]
    float* sred= qbs + NSLOT;                         // [8][8]

    int b   = blockIdx.y;
    int ch  = blockIdx.x;
    int tid = threadIdx.x;
    int w = tid >> 5;
    int l = tid & 31;
    int cb4 = l * 4;

    // sum split-K halves of qk while staging
    for (int i = tid*4; i < NSLOT*DIM; i += 1024) {
        float4 a = *(const float4*)&QK[(size_t)b*NSLOT*DIM + i];
        float4 c = *(const float4*)&QK[(size_t)ROWS*DIM + (size_t)b*NSLOT*DIM + i];
        a.x += c.x; a.y += c.y; a.z += c.z; a.w += c.w;
        *(float4*)&qks[i] = a;
    }
    if (tid < 128) {
        *(float4*)&gbs[tid*4]       = *(const float4*)&g_in[tid*4];
        *(float4*)&gbs[DIM + tid*4] = *(const float4*)&be_in[tid*4];
    }
    if (tid < NSLOT) qbs[tid] = QB[b*NSLOT + tid];
    __syncthreads();

    u64 U2[8];
#pragma unroll
    for (int i = 0; i < 8; i++) U2[i] = 0ull;
    float slp = 0.f;   // per-lane (token,slot) probability accumulator

    const float scale = 0.04419417382415922f;   // 512^-0.5
    int j0 = ch * CTOK;
    int tA = 2*w, tB = 2*w + 1;
    int xoff = w*64 + l*2;
    int myslot = (l >> 1) & 7;

    for (int g = 0; g < CTOK/GTOK; g++) {
        // ======== phase 1: LN + dots for tokens tA,tB ========
        const float* xrA = X + ((size_t)b*NTOK + j0 + g*GTOK + tA)*DIM;
        const float* xrB = xrA + DIM;
        u64 xvA[8], xvB[8];
        u64 sA2 = 0ull, qA2 = 0ull, sB2 = 0ull, qB2 = 0ull;
#pragma unroll
        for (int s = 0; s < 4; s++) {
            ulonglong2 a2 = *(const ulonglong2*)&xrA[s*128 + cb4];
            ulonglong2 b2 = *(const ulonglong2*)&xrB[s*128 + cb4];
            xvA[2*s] = a2.x; xvA[2*s+1] = a2.y;
            xvB[2*s] = b2.x; xvB[2*s+1] = b2.y;
            sA2 = add2_(sA2, a2.x); sA2 = add2_(sA2, a2.y);
            qA2 = fma2_(a2.x, a2.x, qA2); qA2 = fma2_(a2.y, a2.y, qA2);
            sB2 = add2_(sB2, b2.x); sB2 = add2_(sB2, b2.y);
            qB2 = fma2_(b2.x, b2.x, qB2); qB2 = fma2_(b2.y, b2.y, qB2);
        }
        float t0, t1;
        upk2(sA2, t0, t1); float sumA = t0 + t1;
        upk2(qA2, t0, t1); float ssqA = t0 + t1;
        upk2(sB2, t0, t1); float sumB = t0 + t1;
        upk2(qB2, t0, t1); float ssqB = t0 + t1;
#pragma unroll
        for (int off = 16; off > 0; off >>= 1) {
            sumA += __shfl_xor_sync(0xffffffffu, sumA, off);
            ssqA += __shfl_xor_sync(0xffffffffu, ssqA, off);
            sumB += __shfl_xor_sync(0xffffffffu, sumB, off);
            ssqB += __shfl_xor_sync(0xffffffffu, ssqB, off);
        }
        float meanA = sumA * (1.f/DIM);
        float invA  = rsqrtf(ssqA*(1.f/DIM) - meanA*meanA + 1e-5f);
        float meanB = sumB * (1.f/DIM);
        float invB  = rsqrtf(ssqB*(1.f/DIM) - meanB*meanB + 1e-5f);
        u64 invA2 = pk2(invA, invA), nmA2 = pk2(-meanA, -meanA);
        u64 invB2 = pk2(invB, invB), nmB2 = pk2(-meanB, -meanB);

        u64 dA2[8], dB2[8];
#pragma unroll
        for (int i = 0; i < 8; i++) { dA2[i] = 0ull; dB2[i] = 0ull; }
#pragma unroll
        for (int s = 0; s < 4; s++) {
            int c = s*128 + cb4;
            ulonglong2 g2 = *(const ulonglong2*)&gbs[c];
            ulonglong2 b2 = *(const ulonglong2*)&gbs[DIM + c];
            u64 giA0 = mul2_(g2.x, invA2), giA1 = mul2_(g2.y, invA2);
            u64 kA0  = fma2_(nmA2, giA0, b2.x), kA1 = fma2_(nmA2, giA1, b2.y);
            u64 xnA0 = fma2_(xvA[2*s],   giA0, kA0);
            u64 xnA1 = fma2_(xvA[2*s+1], giA1, kA1);
            *(ulonglong2*)&xs[tA*DIM + c] = make_ulonglong2(xnA0, xnA1);
            u64 giB0 = mul2_(g2.x, invB2), giB1 = mul2_(g2.y, invB2);
            u64 kB0  = fma2_(nmB2, giB0, b2.x), kB1 = fma2_(nmB2, giB1, b2.y);
            u64 xnB0 = fma2_(xvB[2*s],   giB0, kB0);
            u64 xnB1 = fma2_(xvB[2*s+1], giB1, kB1);
            *(ulonglong2*)&xs[tB*DIM + c] = make_ulonglong2(xnB0, xnB1);
#pragma unroll
            for (int i = 0; i < 8; i++) {
                ulonglong2 q2 = *(const ulonglong2*)&qks[i*DIM + c];
                dA2[i] = fma2_(q2.x, xnA0, dA2[i]);
                dA2[i] = fma2_(q2.y, xnA1, dA2[i]);
                dB2[i] = fma2_(q2.x, xnB0, dB2[i]);
                dB2[i] = fma2_(q2.y, xnB1, dB2[i]);
            }
        }
        float vA[8], vB[8];
#pragma unroll
        for (int i = 0; i < 8; i++) {
            float a0, a1;
            upk2(dA2[i], a0, a1); vA[i] = a0 + a1;
            upk2(dB2[i], a0, a1); vB[i] = a0 + a1;
        }
        // ---- value-compressing butterfly reduce: 31 shfl, result distributed ----
        float v8[8];
#pragma unroll
        for (int i = 0; i < 8; i++) {
            float sa = vA[i] + __shfl_xor_sync(0xffffffffu, vA[i], 16);
            float sb = vB[i] + __shfl_xor_sync(0xffffffffu, vB[i], 16);
            v8[i] = (l < 16) ? sa : sb;
        }
        float v4[4];
#pragma unroll
        for (int i = 0; i < 4; i++) {
            float a = v8[i]   + __shfl_xor_sync(0xffffffffu, v8[i],   8);
            float c = v8[i+4] + __shfl_xor_sync(0xffffffffu, v8[i+4], 8);
            v4[i] = (l & 8) ? c : a;
        }
        float v2[2];
#pragma unroll
        for (int i = 0; i < 2; i++) {
            float a = v4[i]   + __shfl_xor_sync(0xffffffffu, v4[i],   4);
            float c = v4[i+2] + __shfl_xor_sync(0xffffffffu, v4[i+2], 4);
            v2[i] = (l & 4) ? c : a;
        }
        {
            float a = v2[0] + __shfl_xor_sync(0xffffffffu, v2[0], 2);
            float c = v2[1] + __shfl_xor_sync(0xffffffffu, v2[1], 2);
            v2[0] = (l & 2) ? c : a;
        }
        float d = v2[0] + __shfl_xor_sync(0xffffffffu, v2[0], 1);
        // lane l now holds dot(token = l<16?A:B, slot = (l>>1)&7)
        d = (d + qbs[myslot]) * scale;
        // distributed softmax over the 8 slots within each 16-lane half
        float mx = d;
        mx = fmaxf(mx, __shfl_xor_sync(0xffffffffu, mx, 2));
        mx = fmaxf(mx, __shfl_xor_sync(0xffffffffu, mx, 4));
        mx = fmaxf(mx, __shfl_xor_sync(0xffffffffu, mx, 8));
        float e = __expf(d - mx);
        float se = e;
        se += __shfl_xor_sync(0xffffffffu, se, 2);
        se += __shfl_xor_sync(0xffffffffu, se, 4);
        se += __shfl_xor_sync(0xffffffffu, se, 8);
        float pcur = e / se + 1e-8f;
        slp += pcur;
        if ((l & 1) == 0) {
            int tok = (l < 16) ? tA : tB;
            psd[tok*NSLOT + myslot] = pk2(pcur, pcur);
        }
        __syncthreads();

        // ======== phase 2: warp w accumulates its 64-dim slice for all slots ========
#pragma unroll
        for (int t = 0; t < GTOK; t++) {
            u64 x2 = *(const u64*)&xs[t*DIM + xoff];
            ulonglong2 p01 = *(const ulonglong2*)&psd[t*NSLOT + 0];
            ulonglong2 p23 = *(const ulonglong2*)&psd[t*NSLOT + 2];
            ulonglong2 p45 = *(const ulonglong2*)&psd[t*NSLOT + 4];
            ulonglong2 p67 = *(const ulonglong2*)&psd[t*NSLOT + 6];
            U2[0] = fma2_(p01.x, x2, U2[0]); U2[1] = fma2_(p01.y, x2, U2[1]);
            U2[2] = fma2_(p23.x, x2, U2[2]); U2[3] = fma2_(p23.y, x2, U2[3]);
            U2[4] = fma2_(p45.x, x2, U2[4]); U2[5] = fma2_(p45.y, x2, U2[5]);
            U2[6] = fma2_(p67.x, x2, U2[6]); U2[7] = fma2_(p67.y, x2, U2[7]);
        }
        __syncthreads();
    }

    size_t ub = ((size_t)(b*CH + ch)*NSLOT)*DIM + xoff;
#pragma unroll
    for (int i = 0; i < 8; i++)
        *(u64*)&Upart[ub + (size_t)i*DIM] = U2[i];

    // per-slot S partials: lanes {2s,2s+1,16+2s,16+2s+1} each hold duplicated values
    slp += __shfl_xor_sync(0xffffffffu, slp, 16);
    slp += __shfl_xor_sync(0xffffffffu, slp, 1);
    if ((l & 1) == 0 && l < 16) sred[w*8 + (l >> 1)] = slp * 0.5f;
    __syncthreads();
    if (tid < 8) {
        float s = 0.f;
#pragma unroll
        for (int w2 = 0; w2 < 8; w2++) s += sred[w2*8 + tid];
        Spart[(b*CH + ch)*NSLOT + tid] = s;
    }
}

// ---------------- reduce partials ----------------
__global__ void finish_kernel(const float* __restrict__ Upart,
                              const float* __restrict__ Spart,
                              float* __restrict__ Upre)
{
    int bi = blockIdx.x;
    int b = bi >> 3, i = bi & 7;
    int tid = threadIdx.x;          // 128
    __shared__ float ssum_s;
    if (tid < 32) {
        float s = Spart[(b*CH + tid)*NSLOT + i];
#pragma unroll
        for (int off = 16; off > 0; off >>= 1) s += __shfl_xor_sync(0xffffffffu, s, off);
        if (tid == 0) ssum_s = s;
    }
    __syncthreads();
    float rs = 1.f / ssum_s;
    int c = tid * 4;
    float4 acc = make_float4(0.f,0.f,0.f,0.f);
    for (int chn = 0; chn < CH; chn++) {
        float4 v = *(const float4*)&Upart[(((size_t)b*CH + chn)*NSLOT + i)*DIM + c];
        acc.x += v.x; acc.y += v.y; acc.z += v.z; acc.w += v.w;
    }
    acc.x*=rs; acc.y*=rs; acc.z*=rs; acc.w*=rs;
    *(float4*)&Upre[(size_t)bi*DIM + c] = acc;
}

// ---------------- host orchestration ----------------
extern "C" void kernel_launch(void* const* d_in, const int* in_sizes, int n_in,
                              void* d_out, int out_size)
{
    const float* inputs = (const float*)d_in[0];
    const float* noise  = (const float*)d_in[1];
    const float* mu     = (const float*)d_in[2];
    const float* sg     = (const float*)d_in[3];
    const float* Wq = (const float*)d_in[4];
    const float* bq = (const float*)d_in[5];
    const float* Wk = (const float*)d_in[6];
    const float* bk = (const float*)d_in[7];
    const float* Wv = (const float*)d_in[8];
    const float* bv = (const float*)d_in[9];
    const float* W_ih = (const float*)d_in[10];
    const float* b_ih = (const float*)d_in[11];
    const float* W_hh = (const float*)d_in[12];
    const float* b_hh = (const float*)d_in[13];
    const float* W1 = (const float*)d_in[14];
    const float* b1 = (const float*)d_in[15];
    const float* W2 = (const float*)d_in[16];
    const float* b2 = (const float*)d_in[17];
    const float* gin  = (const float*)d_in[18];
    const float* bein = (const float*)d_in[19];
    const float* gsl  = (const float*)d_in[20];
    const float* besl = (const float*)d_in[21];
    const float* gff  = (const float*)d_in[22];
    const float* beff = (const float*)d_in[23];

    float* slots = (float*)d_out;

    void* p;
    cudaGetSymbolAddress(&p, g_qk);    float* qk    = (float*)p;
    cudaGetSymbolAddress(&p, g_qb);    float* qb    = (float*)p;
    cudaGetSymbolAddress(&p, g_Mqk);   float* Mqk   = (float*)p;
    cudaGetSymbolAddress(&p, g_rqk);   float* rqk   = (float*)p;
    cudaGetSymbolAddress(&p, g_u);     float* uvec  = (float*)p;
    cudaGetSymbolAddress(&p, g_c0);    float* c0    = (float*)p;
    cudaGetSymbolAddress(&p, g_scp);   float* scp   = (float*)p;
    cudaGetSymbolAddress(&p, g_mq);    float* mq    = (float*)p;
    cudaGetSymbolAddress(&p, g_rq);    float* rq    = (float*)p;
    cudaGetSymbolAddress(&p, g_mf);    float* mf    = (float*)p;
    cudaGetSymbolAddress(&p, g_rf);    float* rf    = (float*)p;
    cudaGetSymbolAddress(&p, g_upart); float* upart = (float*)p;
    cudaGetSymbolAddress(&p, g_spart); float* spart = (float*)p;
    cudaGetSymbolAddress(&p, g_upre);  float* upre  = (float*)p;
    cudaGetSymbolAddress(&p, g_upd);   float* upd   = (float*)p;
    cudaGetSymbolAddress(&p, g_gx);    float* gx    = (float*)p;
    cudaGetSymbolAddress(&p, g_gh);    float* gh    = (float*)p;
    cudaGetSymbolAddress(&p, g_h1);    float* h1    = (float*)p;

    static bool attr_done = false;
    if (!attr_done) {
        cudaFuncSetAttribute(attn_kernel2, cudaFuncAttributeMaxDynamicSharedMemorySize, ATTN_SMEM);
        attr_done = true;
    }

    GPtrs Z{};

    init_slots_kernel<<<(ROWS*DIM + 255)/256, 256>>>(noise, mu, sg, slots);
    prologue_kernel<<<9, 128>>>(Wq, Wk, bq, bk, gsl, besl, rqk, uvec, scp, c0);

    // Mqk = Wq^T @ Wk (one-time, unsplit)
    {
        GPtrs a = Z; a.A = Wq; a.B = Wk; a.C = Mqk; a.cstride = 0;
        gemm16<true,false,false,false,1,false><<<dim3(DIM/GBM, DIM/GBN, 1), 128>>>(a, a, DIM, DIM, DIM, DIM);
    }

    for (int it = 0; it < 3; it++) {
        stats_q_kernel<<<ROWS/8, 256>>>(slots, gsl, uvec, scp, c0, mq, rq, qb);
        // qk partials = LN(slots) @ Mqk + rqk   (split-K=2)
        {
            GPtrs a = Z; a.A = slots; a.B = Mqk; a.bias = rqk; a.C = qk; a.cstride = ROWS*DIM;
            a.lnm = mq; a.lnr = rq; a.lng = gsl; a.lnb = besl;
            gemm16<false,false,false,true,2,false><<<dim3(ROWS/GBM, DIM/GBN, 2), 128>>>(a, a, DIM, DIM, DIM, DIM);
        }
        attn_kernel2<<<dim3(CH, BATCH), 256, ATTN_SMEM>>>(inputs, gin, bein, qk, qb, upart, spart);
        finish_kernel<<<ROWS, 128>>>(upart, spart, upre);
        // upd partials = Upre @ Wv^T + bv   (split-K=2)
        {
            GPtrs a = Z; a.A = upre; a.B = Wv; a.bias = bv; a.C = upd; a.cstride = ROWS*DIM;
            gemm16<false,true,false,false,2,false><<<dim3(ROWS/GBM, DIM/GBN, 2), 128>>>(a, a, DIM, DIM, DIM, DIM);
        }
        // GRU gates: gx = (upd0+upd1)@W_ih^T + b_ih ; gh = slots@W_hh^T + b_hh   (pairs x split-K)
        {
            GPtrs a = Z; a.A = upd;   a.A2 = upd + ROWS*DIM; a.B = W_ih; a.bias = b_ih; a.C = gx; a.cstride = ROWS*3*DIM;
            GPtrs b = Z; b.A = slots; b.A2 = nullptr;        b.B = W_hh; b.bias = b_hh; b.C = gh; b.cstride = ROWS*3*DIM;
            gemm16<false,true,false,false,2,false><<<dim3(ROWS/GBM, (3*DIM)/GBN, 4), 128>>>(a, b, DIM, DIM, 3*DIM, DIM);
        }
        gru_ln_kernel<<<ROWS, 128>>>(gx, gh, slots, mf, rf);
        // h1 partials = LN_ff(slots) @ W1^T + b1 (no relu yet; split-K=2)
        {
            GPtrs a = Z; a.A = slots; a.B = W1; a.bias = b1; a.C = h1; a.cstride = ROWS*DIM;
            a.lnm = mf; a.lnr = rf; a.lng = gff; a.lnb = beff;
            gemm16<false,true,false,true,2,false><<<dim3(ROWS/GBM, DIM/GBN, 2), 128>>>(a, a, DIM, DIM, DIM, DIM);
        }
        // slots += relu(h10+h11) @ W2^T + b2   (sum+relu on A load)
        {
            GPtrs a = Z; a.A = h1; a.A2 = h1 + ROWS*DIM; a.B = W2; a.bias = b2; a.res = slots; a.C = slots; a.cstride = 0;
            gemm16<false,true,true,false,1,true><<<dim3(ROWS/GBM, DIM/GBN, 1), 128>>>(a, a, DIM, DIM, DIM, DIM);
        }
    }
}